// round 13
// baseline (speedup 1.0000x reference)
#include <cuda_runtime.h>
#include <cstdint>
#include <climits>
#include <cmath>

#define Bn 8
#define Cc 240
#define Nn 16384
#define Rr 32
#define Vv 32768              // R^3
#define K2 480                // 2*C
#define FS 256                // padded row stride of g_featT
#define MAXROWS (Bn * Nn)     // worst case (131072)

// ---------------- scratch (static device globals; no allocations) ----------------
__device__ float g_featT[(size_t)Bn * Nn * FS];   // CSR-ordered point features [slot][256]
__device__ float g_Y[(size_t)Cc * MAXROWS];       // compact GEMM result, column-major [o][row]
__device__ float g_Wt[Cc * K2];                   // tf32-rounded weights, K interleaved [max16|avg16]
__device__ int   g_cnt[Bn * Vv];
__device__ int   g_idx[Bn * Nn];                  // packed: idx (15b) | arrival (14b)
__device__ int   g_vox2row[Bn * Vv];              // -1 if empty
__device__ int   g_rowoff[MAXROWS];
__device__ int   g_rowcnt[MAXROWS];
__device__ unsigned long long g_bsum[1024];       // packed (rows<<32)|points per 256-voxel block
__device__ int   g_nrows;
__device__ float g_stats[Bn * 4];

__device__ __forceinline__ float tf32r(float x) {
    uint32_t u;
    asm("cvt.rna.tf32.f32 %0, %1;" : "=r"(u) : "f"(x));
    return __uint_as_float(u);
}

__device__ __forceinline__ void mma_tf32(float* c, const uint32_t* a, const uint32_t* b) {
    asm volatile(
        "mma.sync.aligned.m16n8k8.row.col.f32.tf32.tf32.f32 "
        "{%0,%1,%2,%3}, {%4,%5,%6,%7}, {%8,%9}, {%0,%1,%2,%3};"
        : "+f"(c[0]), "+f"(c[1]), "+f"(c[2]), "+f"(c[3])
        : "r"(a[0]), "r"(a[1]), "r"(a[2]), "r"(a[3]), "r"(b[0]), "r"(b[1]));
}

__device__ __forceinline__ void cpasync16(void* smem_ptr, const void* gptr) {
    unsigned s = (unsigned)__cvta_generic_to_shared(smem_ptr);
    asm volatile("cp.async.cg.shared.global [%0], [%1], 16;" :: "r"(s), "l"(gptr));
}
__device__ __forceinline__ void cp_commit() { asm volatile("cp.async.commit_group;"); }
template <int N>
__device__ __forceinline__ void cp_wait() { asm volatile("cp.async.wait_group %0;" :: "n"(N)); }

// ---------------- 0) fused: zero counters + interleaved tf32 W | per-batch stats ----------------
__global__ void __launch_bounds__(1024) init_stats_kernel(const float* __restrict__ W,
                                                          const float* __restrict__ coords) {
    int t = threadIdx.x;
    if (blockIdx.x < 256) {
        int i = blockIdx.x * 1024 + t;                // < B*V
        g_cnt[i] = 0;
        g_vox2row[i] = -1;
        if (i < Cc * K2) {
            // K interleave: k' = 32g+j ; j<16 -> max ch 16g+j ; j>=16 -> avg ch 16g+j-16
            int o = i / K2, k = i - o * K2;
            int g = k >> 5, j = k & 31;
            int src = (j < 16) ? (16 * g + j) : (240 + 16 * g + j - 16);
            g_Wt[i] = tf32r(W[o * K2 + src]);
        }
        return;
    }
    // ---- stats for batch b ----
    int b = blockIdx.x - 256;
    __shared__ float wsm[96];
    __shared__ float smean[3];
    int lane = t & 31, w = t >> 5;
    const float* cx = coords + (size_t)b * 3 * Nn;
    float sx = 0.f, sy = 0.f, sz = 0.f;
    for (int n = t; n < Nn; n += 1024) {
        sx += cx[n];
        sy += cx[Nn + n];
        sz += cx[2 * Nn + n];
    }
#pragma unroll
    for (int d = 16; d; d >>= 1) {
        sx += __shfl_down_sync(0xffffffffu, sx, d);
        sy += __shfl_down_sync(0xffffffffu, sy, d);
        sz += __shfl_down_sync(0xffffffffu, sz, d);
    }
    if (lane == 0) { wsm[w] = sx; wsm[32 + w] = sy; wsm[64 + w] = sz; }
    __syncthreads();
    if (w == 0) {
        float a = wsm[lane], bb = wsm[32 + lane], c = wsm[64 + lane];
#pragma unroll
        for (int d = 16; d; d >>= 1) {
            a += __shfl_down_sync(0xffffffffu, a, d);
            bb += __shfl_down_sync(0xffffffffu, bb, d);
            c += __shfl_down_sync(0xffffffffu, c, d);
        }
        if (lane == 0) {
            smean[0] = a / (float)Nn;
            smean[1] = bb / (float)Nn;
            smean[2] = c / (float)Nn;
        }
    }
    __syncthreads();
    float mx = smean[0], my = smean[1], mz = smean[2];
    float mn = 0.f;
    for (int n = t; n < Nn; n += 1024) {
        float x = cx[n] - mx, y = cx[Nn + n] - my, z = cx[2 * Nn + n] - mz;
        mn = fmaxf(mn, sqrtf(x * x + y * y + z * z));
    }
#pragma unroll
    for (int d = 16; d; d >>= 1) mn = fmaxf(mn, __shfl_down_sync(0xffffffffu, mn, d));
    if (lane == 0) wsm[w] = mn;
    __syncthreads();
    if (w == 0) {
        float a = wsm[lane];
#pragma unroll
        for (int d = 16; d; d >>= 1) a = fmaxf(a, __shfl_down_sync(0xffffffffu, a, d));
        if (lane == 0) {
            g_stats[b * 4 + 0] = mx;
            g_stats[b * 4 + 1] = my;
            g_stats[b * 4 + 2] = mz;
            g_stats[b * 4 + 3] = a * 2.0f;   // denom (EPS = 0)
        }
    }
}

// ---------------- 1) normalized coords + packed voxel idx/arrival + counts ----------------
__global__ void points_kernel(const float* __restrict__ coords, float* __restrict__ nc_out) {
    int i = blockIdx.x * blockDim.x + threadIdx.x;   // < B*N
    int b = i >> 14;
    int n = i & (Nn - 1);
    float mx = g_stats[b * 4 + 0], my = g_stats[b * 4 + 1];
    float mz = g_stats[b * 4 + 2], dn = g_stats[b * 4 + 3];
    const float* cb = coords + (size_t)b * 3 * Nn;
    float x = cb[n], y = cb[Nn + n], z = cb[2 * Nn + n];

    float ncx = ((x - mx) / dn + 0.5f) * (float)Rr;
    float ncy = ((y - my) / dn + 0.5f) * (float)Rr;
    float ncz = ((z - mz) / dn + 0.5f) * (float)Rr;
    ncx = fminf(fmaxf(ncx, 0.f), (float)(Rr - 1));
    ncy = fminf(fmaxf(ncy, 0.f), (float)(Rr - 1));
    ncz = fminf(fmaxf(ncz, 0.f), (float)(Rr - 1));

    float* nb = nc_out + (size_t)b * 3 * Nn;
    nb[n] = ncx;
    nb[Nn + n] = ncy;
    nb[2 * Nn + n] = ncz;

    int vx = (int)rintf(ncx);   // round-half-even == jnp.round
    int vy = (int)rintf(ncy);
    int vz = (int)rintf(ncz);
    int idx = vx * (Rr * Rr) + vy * Rr + vz;
    int arr = atomicAdd(&g_cnt[b * Vv + idx], 1);    // arrival index (order-independent content)
    g_idx[i] = idx | (arr << 15);
}

// ---------------- 2a) block totals (256 voxels/block) ----------------
__global__ void scan1_kernel() {
    int blk = blockIdx.x, t = threadIdx.x;
    int cnt = g_cnt[blk * 256 + t];
    unsigned long long v = ((unsigned long long)(cnt > 0) << 32) | (unsigned)cnt;
#pragma unroll
    for (int d = 16; d; d >>= 1) v += __shfl_down_sync(0xffffffffu, v, d);
    __shared__ unsigned long long w[8];
    if ((t & 31) == 0) w[t >> 5] = v;
    __syncthreads();
    if (t == 0) {
        unsigned long long s = 0;
#pragma unroll
        for (int i = 0; i < 8; ++i) s += w[i];
        g_bsum[blk] = s;
    }
}

// ---------------- 2b) rows+offsets: every block redundantly scans the 1024 bsums ----------------
__global__ void scan3_kernel() {
    int blk = blockIdx.x, t = threadIdx.x, lane = t & 31, w = t >> 5;

    __shared__ unsigned long long part[256];
    {
        const unsigned long long* bs = g_bsum + 4 * t;
        part[t] = bs[0] + bs[1] + bs[2] + bs[3];
    }
    __syncthreads();
    unsigned long long x = part[t];
#pragma unroll
    for (int d = 1; d < 32; d <<= 1) {
        unsigned long long y = __shfl_up_sync(0xffffffffu, x, d);
        if (lane >= d) x += y;
    }
    __shared__ unsigned long long wsum[8];
    if (lane == 31) wsum[w] = x;
    __syncthreads();
    __shared__ unsigned long long wexc[8];
    if (t < 8) {
        unsigned long long s = 0;
        for (int i = 0; i < t; ++i) s += wsum[i];
        wexc[t] = s;
    }
    __syncthreads();
    __shared__ unsigned long long s_base, s_total;
    if (t == (blk >> 2)) {
        unsigned long long excl_chunk = x - part[t] + wexc[w];
        const unsigned long long* bs = g_bsum + (blk & ~3);
        for (int i = 0; i < (blk & 3); ++i) excl_chunk += bs[i];
        s_base = excl_chunk;
    }
    if (t == 255) s_total = x + wexc[7];
    __syncthreads();
    if (blk == 0 && t == 0) g_nrows = (int)(s_total >> 32);

    int bv = blk * 256 + t;
    int cnt = g_cnt[bv];
    unsigned long long v = ((unsigned long long)(cnt > 0) << 32) | (unsigned)cnt;
    unsigned long long orig = v;
#pragma unroll
    for (int d = 1; d < 32; d <<= 1) {
        unsigned long long y = __shfl_up_sync(0xffffffffu, v, d);
        if (lane >= d) v += y;
    }
    __syncthreads();
    if (lane == 31) wsum[w] = v;
    __syncthreads();
    if (t < 8) {
        unsigned long long s = 0;
        for (int i = 0; i < t; ++i) s += wsum[i];
        wexc[t] = s;
    }
    __syncthreads();
    unsigned long long excl = v - orig + wexc[w] + s_base;
    if (cnt > 0) {
        int row = (int)(excl >> 32);
        int off = (int)(excl & 0xffffffffu);
        g_vox2row[bv] = row;
        g_rowcnt[row] = cnt;
        g_rowoff[row] = off;
    }
}

// ---------------- 3) gather-transpose: coalesced stores + smem swizzle (R11 form) -------------
__global__ void __launch_bounds__(256) gtrans_kernel(const float* __restrict__ f) {
    __shared__ float4 sm4[48][32];
    __shared__ int s_slot[128];
    int b = blockIdx.z;
    int n0 = blockIdx.x << 7;
    int c0 = blockIdx.y * 48;
    int t = threadIdx.x;

    if (t < 128) {
        int pk = g_idx[(b << 14) + n0 + t];
        int idx = pk & 0x7fff;
        int row = g_vox2row[b * Vv + idx];
        s_slot[t] = g_rowoff[row] + (pk >> 15);
    }

    int col4 = t & 31, r0 = t >> 5;
#pragma unroll
    for (int rr = 0; rr < 6; ++rr) {
        int r = r0 + rr * 8;
        float4 v = __ldcs(reinterpret_cast<const float4*>(
            f + ((size_t)b * Cc + c0 + r) * Nn + n0 + col4 * 4));
        sm4[r][(col4 + r + (r >> 2)) & 31] = v;
    }
    __syncthreads();

    const float* smf = reinterpret_cast<const float*>(sm4);
#pragma unroll
    for (int it = 0; it < 6; ++it) {
        int w = it * 256 + t;
        int j = w % 12;
        int p = w / 12;
        int pq = p >> 2, pk = p & 3;
        float o[4];
#pragma unroll
        for (int kk = 0; kk < 4; ++kk) {
            int r = 4 * j + kk;
            o[kk] = smf[r * 128 + (((pq + r + (r >> 2)) & 31) << 2) + pk];
        }
        *reinterpret_cast<float4*>(g_featT + (size_t)s_slot[p] * FS + c0 + 4 * j) =
            make_float4(o[0], o[1], o[2], o[3]);
    }
}

// ---------------- 4) fused reduce+GEMM: max/avg computed in-kernel from g_featT ---------------
// BM=128, BN=240, BK=32 (= 16 channels interleaved [max16|avg16]); 384 threads, 12 warps.
// Trailing __syncthreads() per k-iter is LOAD-BEARING: it keeps next iter's cp.async (Bs)
// from overwriting a buffer slower warps are still MMA-reading (the R12 bug).
#define AS(s, r, k) As[(((s) * 128 + (r)) * 36) + (k)]
#define BS(s, r, k) Bsm[(((s) * 240 + (r)) * 36) + (k)]
#define GEMM_SMEM ((2 * 128 * 36 + 2 * 240 * 36 + 2 * 240 + 2 * 128) * 4)
#define GEMM_GRID 296

__global__ void __launch_bounds__(384) gemm_kernel(
    const float* __restrict__ bias,
    const float* __restrict__ gamma,
    const float* __restrict__ beta,
    const float* __restrict__ bmean,
    const float* __restrict__ bvar)
{
    int nrows = g_nrows;
    int ntiles = (nrows + 127) >> 7;

    extern __shared__ float dsm[];
    float* As  = dsm;                       // [2][128][36]
    float* Bsm = dsm + 2 * 128 * 36;        // [2][240][36]
    float* sc_s = Bsm + 2 * 240 * 36;       // [240]
    float* sc_o = sc_s + 240;
    int* s_off = reinterpret_cast<int*>(sc_o + 240);   // [128]
    int* s_cnt = s_off + 128;                           // [128]

    int tid = threadIdx.x;

    if (tid < 240) {
        float s = gamma[tid] * rsqrtf(bvar[tid] + 1e-5f);
        sc_s[tid] = s;
        sc_o[tid] = (bias[tid] - bmean[tid]) * s + beta[tid];
    }

    int lane = tid & 31, warp = tid >> 5;
    int wm = warp & 3, wn = warp >> 2;        // 4 M-warps x 3 N-warps
    int grp = lane >> 2, qk = lane & 3;

    // A-prep: thread (row = tid>>1, half = tid&1) reduces 8 channels of its row.
    int arow = tid >> 1, ahalf = tid & 1;

    auto prepA = [&](int g, int s) {
        if (tid < 256) {
            int cnt = s_cnt[arow];
            const float4* bp = reinterpret_cast<const float4*>(
                g_featT + (size_t)s_off[arow] * FS + 16 * g + 8 * ahalf);
            float mx[8], sm[8];
#pragma unroll
            for (int c = 0; c < 8; ++c) { mx[c] = 0.f; sm[c] = 0.f; }
            if (cnt > 0) {
#pragma unroll
                for (int c = 0; c < 8; ++c) mx[c] = -INFINITY;
                for (int p = 0; p < cnt; ++p) {
                    float4 a = __ldcs(bp + (size_t)p * (FS / 4));
                    float4 b2 = __ldcs(bp + (size_t)p * (FS / 4) + 1);
                    mx[0] = fmaxf(mx[0], a.x);  sm[0] += a.x;
                    mx[1] = fmaxf(mx[1], a.y);  sm[1] += a.y;
                    mx[2] = fmaxf(mx[2], a.z);  sm[2] += a.z;
                    mx[3] = fmaxf(mx[3], a.w);  sm[3] += a.w;
                    mx[4] = fmaxf(mx[4], b2.x); sm[4] += b2.x;
                    mx[5] = fmaxf(mx[5], b2.y); sm[5] += b2.y;
                    mx[6] = fmaxf(mx[6], b2.z); sm[6] += b2.z;
                    mx[7] = fmaxf(mx[7], b2.w); sm[7] += b2.w;
                }
                float inv = 1.0f / (float)cnt;
#pragma unroll
                for (int c = 0; c < 8; ++c) sm[c] *= inv;
            }
            int kb = 8 * ahalf;
            *reinterpret_cast<float4*>(&AS(s, arow, kb)) =
                make_float4(tf32r(mx[0]), tf32r(mx[1]), tf32r(mx[2]), tf32r(mx[3]));
            *reinterpret_cast<float4*>(&AS(s, arow, kb + 4)) =
                make_float4(tf32r(mx[4]), tf32r(mx[5]), tf32r(mx[6]), tf32r(mx[7]));
            *reinterpret_cast<float4*>(&AS(s, arow, 16 + kb)) =
                make_float4(tf32r(sm[0]), tf32r(sm[1]), tf32r(sm[2]), tf32r(sm[3]));
            *reinterpret_cast<float4*>(&AS(s, arow, 16 + kb + 4)) =
                make_float4(tf32r(sm[4]), tf32r(sm[5]), tf32r(sm[6]), tf32r(sm[7]));
        }
    };

    auto loadB = [&](int g, int s) {
        int kg = g * 32;
#pragma unroll
        for (int i = 0; i < 5; ++i) {
            int idx = tid + 384 * i;              // < 1920
            int rowb = idx >> 3;
            int c4 = (idx & 7) << 2;
            cpasync16(&BS(s, rowb, c4), g_Wt + (size_t)rowb * K2 + kg + c4);
        }
        cp_commit();
    };

    bool first = true;
    for (int tile = blockIdx.x; tile < ntiles; tile += GEMM_GRID) {
        int row0 = tile << 7;

        if (!first) __syncthreads();       // previous tile fully done before smem reuse
        first = false;

        if (tid < 128) {
            int r = row0 + tid;
            bool v = r < nrows;
            s_cnt[tid] = v ? g_rowcnt[r] : 0;
            s_off[tid] = v ? g_rowoff[r] : 0;
        }
        loadB(0, 0);
        __syncthreads();                   // metadata visible
        prepA(0, 0);

        float acc[2][10][4];
#pragma unroll
        for (int mt = 0; mt < 2; ++mt)
#pragma unroll
            for (int nt = 0; nt < 10; ++nt)
#pragma unroll
                for (int q = 0; q < 4; ++q) acc[mt][nt][q] = 0.f;

        for (int g = 0; g < 15; ++g) {
            int s = g & 1;
            if (g < 14) loadB(g + 1, s ^ 1);
            if (g < 14) { cp_wait<1>(); } else { cp_wait<0>(); }
            __syncthreads();               // As[s] STS + Bs[s] cp.async visible

#pragma unroll
            for (int ks = 0; ks < 4; ++ks) {
                int k8 = ks * 8;
                uint32_t a[2][4], b[10][2];
#pragma unroll
                for (int mt = 0; mt < 2; ++mt) {
                    int r = wm * 32 + mt * 16 + grp;
                    a[mt][0] = __float_as_uint(AS(s, r, k8 + qk));
                    a[mt][1] = __float_as_uint(AS(s, r + 8, k8 + qk));
                    a[mt][2] = __float_as_uint(AS(s, r, k8 + qk + 4));
                    a[mt][3] = __float_as_uint(AS(s, r + 8, k8 + qk + 4));
                }
#pragma unroll
                for (int nt = 0; nt < 10; ++nt) {
                    int nc = wn * 80 + nt * 8 + grp;
                    b[nt][0] = __float_as_uint(BS(s, nc, k8 + qk));
                    b[nt][1] = __float_as_uint(BS(s, nc, k8 + qk + 4));
                }
#pragma unroll
                for (int mt = 0; mt < 2; ++mt)
#pragma unroll
                    for (int nt = 0; nt < 10; ++nt)
                        mma_tf32(acc[mt][nt], a[mt], b[nt]);
            }
            if (g < 14) prepA(g + 1, s ^ 1);   // writes As[s^1]
            __syncthreads();               // ALL MMA(g) readers done before loadB(g+2) overwrites Bs
        }

        // epilogue: BN + swish -> compact g_Y[o][row]
#pragma unroll
        for (int mt = 0; mt < 2; ++mt) {
            int r0 = row0 + wm * 32 + mt * 16 + grp;
            int r1 = r0 + 8;
            bool v0 = r0 < nrows, v1 = r1 < nrows;
#pragma unroll
            for (int nt = 0; nt < 10; ++nt) {
                int ocl = wn * 80 + nt * 8 + 2 * qk;
#pragma unroll
                for (int h = 0; h < 2; ++h) {
                    int o = ocl + h;
                    float s = sc_s[o], off = sc_o[o];
                    size_t ocol = (size_t)o * MAXROWS;
                    if (v0) {
                        float y = acc[mt][nt][h] * s + off;
                        g_Y[ocol + r0] = y / (1.0f + expf(-y));
                    }
                    if (v1) {
                        float y = acc[mt][nt][2 + h] * s + off;
                        g_Y[ocol + r1] = y / (1.0f + expf(-y));
                    }
                }
            }
        }
    }
}

// ---------------- 5) final output: coalesced merge of g_Y + empty constants ----------------
__global__ void __launch_bounds__(256) write_out_kernel(
    const float* __restrict__ bias,
    const float* __restrict__ gamma,
    const float* __restrict__ beta,
    const float* __restrict__ bmean,
    const float* __restrict__ bvar,
    float* __restrict__ out)          // [B][240][V]
{
    __shared__ float s_empty[60];
    int t = threadIdx.x;
    int span = blockIdx.x;            // < B*V/1024
    int o0 = blockIdx.y * 60;
    int b = span >> 5;                // 32 spans per batch
    int v0 = (span & 31) << 10;

    if (t < 60) {
        int o = o0 + t;
        float s = gamma[o] * rsqrtf(bvar[o] + 1e-5f);
        float y = (bias[o] - bmean[o]) * s + beta[o];
        s_empty[t] = y / (1.0f + expf(-y));
    }
    int4 rows = *reinterpret_cast<const int4*>(g_vox2row + b * Vv + v0 + 4 * t);
    __syncthreads();

    size_t obase = (size_t)b * Cc * Vv + v0 + 4 * t;
    for (int j = 0; j < 60; ++j) {
        int o = o0 + j;
        float e = s_empty[j];
        const float* ycol = g_Y + (size_t)o * MAXROWS;
        float4 r;
        r.x = (rows.x >= 0) ? ycol[rows.x] : e;
        r.y = (rows.y >= 0) ? ycol[rows.y] : e;
        r.z = (rows.z >= 0) ? ycol[rows.z] : e;
        r.w = (rows.w >= 0) ? ycol[rows.w] : e;
        __stcs(reinterpret_cast<float4*>(out + obase + (size_t)o * Vv), r);
    }
}

// ---------------- launch ----------------
extern "C" void kernel_launch(void* const* d_in, const int* in_sizes, int n_in,
                              void* d_out, int out_size) {
    const float* features = (const float*)d_in[0];
    const float* coords   = (const float*)d_in[1];
    const float* conv_w   = (const float*)d_in[2];
    const float* conv_b   = (const float*)d_in[3];
    const float* bn_gamma = (const float*)d_in[4];
    const float* bn_beta  = (const float*)d_in[5];
    const float* bn_mean  = (const float*)d_in[6];
    const float* bn_var   = (const float*)d_in[7];

    float* out = (float*)d_out;                       // [B, C, R^3]
    float* nc_out = out + (size_t)Bn * Cc * Vv;       // [B, 3, N]

    cudaFuncSetAttribute(gemm_kernel, cudaFuncAttributeMaxDynamicSharedMemorySize, GEMM_SMEM);

    init_stats_kernel<<<264, 1024>>>(conv_w, coords);
    points_kernel<<<(Bn * Nn) / 256, 256>>>(coords, nc_out);
    scan1_kernel<<<1024, 256>>>();
    scan3_kernel<<<1024, 256>>>();
    gtrans_kernel<<<dim3(Nn / 128, 5, Bn), 256>>>(features);
    gemm_kernel<<<GEMM_GRID, 384, GEMM_SMEM>>>(conv_b, bn_gamma, bn_beta,
                                               bn_mean, bn_var);
    write_out_kernel<<<dim3((Bn * Vv) / 1024, 4), 256>>>(conv_b, bn_gamma, bn_beta,
                                                         bn_mean, bn_var, out);
}

// round 14
// speedup vs baseline: 1.4079x; 1.4079x over previous
#include <cuda_runtime.h>
#include <cstdint>
#include <climits>
#include <cmath>

#define Bn 8
#define Cc 240
#define Nn 16384
#define Rr 32
#define Vv 32768              // R^3
#define K2 480                // 2*C
#define FS 256                // padded row stride of g_featT
#define MAXROWS (Bn * Nn)     // worst case (131072)

// ---------------- scratch (static device globals; no allocations) ----------------
__device__ float g_featT[(size_t)Bn * Nn * FS];   // CSR-ordered point features [slot][256]
__device__ float g_A[(size_t)MAXROWS * K2];       // compact GEMM A (tf32-rounded)
__device__ float g_Y[(size_t)Cc * MAXROWS];       // compact GEMM result, column-major [o][row]
__device__ float g_Wt[Cc * K2];                   // tf32-rounded weights
__device__ int   g_cnt[Bn * Vv];
__device__ int   g_idx[Bn * Nn];                  // packed: idx (15b) | arrival (14b)
__device__ int   g_vox2row[Bn * Vv];              // -1 if empty
__device__ int   g_rowoff[MAXROWS];
__device__ int   g_rowcnt[MAXROWS];
__device__ unsigned long long g_bsum[1024];       // packed (rows<<32)|points per 256-voxel block
__device__ int   g_nrows;
__device__ float g_stats[Bn * 4];

__device__ __forceinline__ float tf32r(float x) {
    uint32_t u;
    asm("cvt.rna.tf32.f32 %0, %1;" : "=r"(u) : "f"(x));
    return __uint_as_float(u);
}

__device__ __forceinline__ void mma_tf32(float* c, const uint32_t* a, const uint32_t* b) {
    asm volatile(
        "mma.sync.aligned.m16n8k8.row.col.f32.tf32.tf32.f32 "
        "{%0,%1,%2,%3}, {%4,%5,%6,%7}, {%8,%9}, {%0,%1,%2,%3};"
        : "+f"(c[0]), "+f"(c[1]), "+f"(c[2]), "+f"(c[3])
        : "r"(a[0]), "r"(a[1]), "r"(a[2]), "r"(a[3]), "r"(b[0]), "r"(b[1]));
}

__device__ __forceinline__ void cpasync16(void* smem_ptr, const void* gptr) {
    unsigned s = (unsigned)__cvta_generic_to_shared(smem_ptr);
    asm volatile("cp.async.cg.shared.global [%0], [%1], 16;" :: "r"(s), "l"(gptr));
}
__device__ __forceinline__ void cp_commit() { asm volatile("cp.async.commit_group;"); }
template <int N>
__device__ __forceinline__ void cp_wait() { asm volatile("cp.async.wait_group %0;" :: "n"(N)); }

// ---------------- 0) fused: zero counters + tf32 W (blocks 0-255) | per-batch stats (256-263) ----
__global__ void __launch_bounds__(1024) init_stats_kernel(const float* __restrict__ W,
                                                          const float* __restrict__ coords) {
    int t = threadIdx.x;
    if (blockIdx.x < 256) {
        int i = blockIdx.x * 1024 + t;                // < B*V
        g_cnt[i] = 0;
        g_vox2row[i] = -1;
        if (i < Cc * K2) g_Wt[i] = tf32r(W[i]);
        return;
    }
    // ---- stats for batch b ----
    int b = blockIdx.x - 256;
    __shared__ float wsm[96];
    __shared__ float smean[3];
    int lane = t & 31, w = t >> 5;
    const float* cx = coords + (size_t)b * 3 * Nn;
    float sx = 0.f, sy = 0.f, sz = 0.f;
    for (int n = t; n < Nn; n += 1024) {
        sx += cx[n];
        sy += cx[Nn + n];
        sz += cx[2 * Nn + n];
    }
#pragma unroll
    for (int d = 16; d; d >>= 1) {
        sx += __shfl_down_sync(0xffffffffu, sx, d);
        sy += __shfl_down_sync(0xffffffffu, sy, d);
        sz += __shfl_down_sync(0xffffffffu, sz, d);
    }
    if (lane == 0) { wsm[w] = sx; wsm[32 + w] = sy; wsm[64 + w] = sz; }
    __syncthreads();
    if (w == 0) {
        float a = wsm[lane], bb = wsm[32 + lane], c = wsm[64 + lane];
#pragma unroll
        for (int d = 16; d; d >>= 1) {
            a += __shfl_down_sync(0xffffffffu, a, d);
            bb += __shfl_down_sync(0xffffffffu, bb, d);
            c += __shfl_down_sync(0xffffffffu, c, d);
        }
        if (lane == 0) {
            smean[0] = a / (float)Nn;
            smean[1] = bb / (float)Nn;
            smean[2] = c / (float)Nn;
        }
    }
    __syncthreads();
    float mx = smean[0], my = smean[1], mz = smean[2];
    float mn = 0.f;
    for (int n = t; n < Nn; n += 1024) {
        float x = cx[n] - mx, y = cx[Nn + n] - my, z = cx[2 * Nn + n] - mz;
        mn = fmaxf(mn, sqrtf(x * x + y * y + z * z));
    }
#pragma unroll
    for (int d = 16; d; d >>= 1) mn = fmaxf(mn, __shfl_down_sync(0xffffffffu, mn, d));
    if (lane == 0) wsm[w] = mn;
    __syncthreads();
    if (w == 0) {
        float a = wsm[lane];
#pragma unroll
        for (int d = 16; d; d >>= 1) a = fmaxf(a, __shfl_down_sync(0xffffffffu, a, d));
        if (lane == 0) {
            g_stats[b * 4 + 0] = mx;
            g_stats[b * 4 + 1] = my;
            g_stats[b * 4 + 2] = mz;
            g_stats[b * 4 + 3] = a * 2.0f;   // denom (EPS = 0)
        }
    }
}

// ---------------- 1) normalized coords + packed voxel idx/arrival + counts ----------------
__global__ void points_kernel(const float* __restrict__ coords, float* __restrict__ nc_out) {
    int i = blockIdx.x * blockDim.x + threadIdx.x;   // < B*N
    int b = i >> 14;
    int n = i & (Nn - 1);
    float mx = g_stats[b * 4 + 0], my = g_stats[b * 4 + 1];
    float mz = g_stats[b * 4 + 2], dn = g_stats[b * 4 + 3];
    const float* cb = coords + (size_t)b * 3 * Nn;
    float x = cb[n], y = cb[Nn + n], z = cb[2 * Nn + n];

    float ncx = ((x - mx) / dn + 0.5f) * (float)Rr;
    float ncy = ((y - my) / dn + 0.5f) * (float)Rr;
    float ncz = ((z - mz) / dn + 0.5f) * (float)Rr;
    ncx = fminf(fmaxf(ncx, 0.f), (float)(Rr - 1));
    ncy = fminf(fmaxf(ncy, 0.f), (float)(Rr - 1));
    ncz = fminf(fmaxf(ncz, 0.f), (float)(Rr - 1));

    float* nb = nc_out + (size_t)b * 3 * Nn;
    nb[n] = ncx;
    nb[Nn + n] = ncy;
    nb[2 * Nn + n] = ncz;

    int vx = (int)rintf(ncx);   // round-half-even == jnp.round
    int vy = (int)rintf(ncy);
    int vz = (int)rintf(ncz);
    int idx = vx * (Rr * Rr) + vy * Rr + vz;
    int arr = atomicAdd(&g_cnt[b * Vv + idx], 1);    // arrival index (order-independent content)
    g_idx[i] = idx | (arr << 15);
}

// ---------------- 2a) block totals (256 voxels/block) ----------------
__global__ void scan1_kernel() {
    int blk = blockIdx.x, t = threadIdx.x;
    int cnt = g_cnt[blk * 256 + t];
    unsigned long long v = ((unsigned long long)(cnt > 0) << 32) | (unsigned)cnt;
#pragma unroll
    for (int d = 16; d; d >>= 1) v += __shfl_down_sync(0xffffffffu, v, d);
    __shared__ unsigned long long w[8];
    if ((t & 31) == 0) w[t >> 5] = v;
    __syncthreads();
    if (t == 0) {
        unsigned long long s = 0;
#pragma unroll
        for (int i = 0; i < 8; ++i) s += w[i];
        g_bsum[blk] = s;
    }
}

// ---------------- 2b) rows+offsets: every block redundantly scans the 1024 bsums ----------------
__global__ void scan3_kernel() {
    int blk = blockIdx.x, t = threadIdx.x, lane = t & 31, w = t >> 5;

    __shared__ unsigned long long part[256];
    {
        const unsigned long long* bs = g_bsum + 4 * t;
        part[t] = bs[0] + bs[1] + bs[2] + bs[3];
    }
    __syncthreads();
    unsigned long long x = part[t];
#pragma unroll
    for (int d = 1; d < 32; d <<= 1) {
        unsigned long long y = __shfl_up_sync(0xffffffffu, x, d);
        if (lane >= d) x += y;
    }
    __shared__ unsigned long long wsum[8];
    if (lane == 31) wsum[w] = x;
    __syncthreads();
    __shared__ unsigned long long wexc[8];
    if (t < 8) {
        unsigned long long s = 0;
        for (int i = 0; i < t; ++i) s += wsum[i];
        wexc[t] = s;
    }
    __syncthreads();
    __shared__ unsigned long long s_base, s_total;
    if (t == (blk >> 2)) {
        unsigned long long excl_chunk = x - part[t] + wexc[w];
        const unsigned long long* bs = g_bsum + (blk & ~3);
        for (int i = 0; i < (blk & 3); ++i) excl_chunk += bs[i];
        s_base = excl_chunk;
    }
    if (t == 255) s_total = x + wexc[7];
    __syncthreads();
    if (blk == 0 && t == 0) g_nrows = (int)(s_total >> 32);

    int bv = blk * 256 + t;
    int cnt = g_cnt[bv];
    unsigned long long v = ((unsigned long long)(cnt > 0) << 32) | (unsigned)cnt;
    unsigned long long orig = v;
#pragma unroll
    for (int d = 1; d < 32; d <<= 1) {
        unsigned long long y = __shfl_up_sync(0xffffffffu, v, d);
        if (lane >= d) v += y;
    }
    __syncthreads();
    if (lane == 31) wsum[w] = v;
    __syncthreads();
    if (t < 8) {
        unsigned long long s = 0;
        for (int i = 0; i < t; ++i) s += wsum[i];
        wexc[t] = s;
    }
    __syncthreads();
    unsigned long long excl = v - orig + wexc[w] + s_base;
    if (cnt > 0) {
        int row = (int)(excl >> 32);
        int off = (int)(excl & 0xffffffffu);
        g_vox2row[bv] = row;
        g_rowcnt[row] = cnt;
        g_rowoff[row] = off;
    }
}

// ---------------- 3) gather-transpose: coalesced stores + improved smem swizzle --------------
// Placement column for logical (r, pq): (pq + r + (r>>2)) & 31  ->  read-phase conflicts 6->2-way.
__global__ void __launch_bounds__(256) gtrans_kernel(const float* __restrict__ f) {
    __shared__ float4 sm4[48][32];
    __shared__ int s_slot[128];
    int b = blockIdx.z;
    int n0 = blockIdx.x << 7;
    int c0 = blockIdx.y * 48;
    int t = threadIdx.x;

    if (t < 128) {
        int pk = g_idx[(b << 14) + n0 + t];
        int idx = pk & 0x7fff;
        int row = g_vox2row[b * Vv + idx];
        s_slot[t] = g_rowoff[row] + (pk >> 15);
    }

    int col4 = t & 31, r0 = t >> 5;
#pragma unroll
    for (int rr = 0; rr < 6; ++rr) {
        int r = r0 + rr * 8;
        float4 v = __ldcs(reinterpret_cast<const float4*>(
            f + ((size_t)b * Cc + c0 + r) * Nn + n0 + col4 * 4));
        sm4[r][(col4 + r + (r >> 2)) & 31] = v;
    }
    __syncthreads();

    const float* smf = reinterpret_cast<const float*>(sm4);
#pragma unroll
    for (int it = 0; it < 6; ++it) {
        int w = it * 256 + t;
        int j = w % 12;
        int p = w / 12;
        int pq = p >> 2, pk = p & 3;
        float o[4];
#pragma unroll
        for (int kk = 0; kk < 4; ++kk) {
            int r = 4 * j + kk;
            o[kk] = smf[r * 128 + (((pq + r + (r >> 2)) & 31) << 2) + pk];
        }
        *reinterpret_cast<float4*>(g_featT + (size_t)s_slot[p] * FS + c0 + 4 * j) =
            make_float4(o[0], o[1], o[2], o[3]);
    }
}

// ---------------- 4) reduce: 4 row-groups per block, CSR rows -> tf32-rounded A ----------------
__global__ void __launch_bounds__(256) reduce_kernel() {
    int nrows = g_nrows;
    int t = threadIdx.x & 63;            // lane within group
    int grpi = threadIdx.x >> 6;         // 0..3
    if (t >= 60) return;
    for (int row = blockIdx.x * 4 + grpi; row < nrows; row += gridDim.x * 4) {
        int cnt = g_rowcnt[row];
        int off = g_rowoff[row];
        const float4* base = reinterpret_cast<const float4*>(
            g_featT + (size_t)off * FS + 4 * t);
        float4 s = make_float4(0.f, 0.f, 0.f, 0.f);
        float4 m = make_float4(-INFINITY, -INFINITY, -INFINITY, -INFINITY);
        for (int p = 0; p < cnt; ++p) {
            float4 v = __ldcs(base + (size_t)p * (FS / 4));
            s.x += v.x; s.y += v.y; s.z += v.z; s.w += v.w;
            m.x = fmaxf(m.x, v.x); m.y = fmaxf(m.y, v.y);
            m.z = fmaxf(m.z, v.z); m.w = fmaxf(m.w, v.w);
        }
        float inv = 1.0f / (float)cnt;
        float* arow = g_A + (size_t)row * K2;
        *reinterpret_cast<float4*>(arow + 4 * t) =
            make_float4(tf32r(m.x), tf32r(m.y), tf32r(m.z), tf32r(m.w));
        *reinterpret_cast<float4*>(arow + Cc + 4 * t) =
            make_float4(tf32r(s.x * inv), tf32r(s.y * inv), tf32r(s.z * inv), tf32r(s.w * inv));
    }
}

// ---------------- 5) tf32 GEMM single-pass N=240, persistent grid -> g_Y[o][row] ----------------
// BM=128, BN=240, BK=32; 384 threads = 12 warps (4M x 3N); warp tile 32x80.
#define AS(s, r, k) As[(((s) * 128 + (r)) * 36) + (k)]
#define BS(s, r, k) Bsm[(((s) * 240 + (r)) * 36) + (k)]
#define GEMM_SMEM ((2 * 128 * 36 + 2 * 240 * 36 + 2 * 240) * 4)
#define GEMM_GRID 296

__global__ void __launch_bounds__(384) gemm_kernel(
    const float* __restrict__ bias,
    const float* __restrict__ gamma,
    const float* __restrict__ beta,
    const float* __restrict__ bmean,
    const float* __restrict__ bvar)
{
    int nrows = g_nrows;
    int ntiles = (nrows + 127) >> 7;

    extern __shared__ float dsm[];
    float* As  = dsm;                       // [2][128][36]
    float* Bsm = dsm + 2 * 128 * 36;        // [2][240][36]
    float* sc_s = Bsm + 2 * 240 * 36;       // [240]
    float* sc_o = sc_s + 240;

    int tid = threadIdx.x;

    if (tid < 240) {
        float s = gamma[tid] * rsqrtf(bvar[tid] + 1e-5f);
        sc_s[tid] = s;
        sc_o[tid] = (bias[tid] - bmean[tid]) * s + beta[tid];
    }

    int lane = tid & 31, warp = tid >> 5;
    int wm = warp & 3, wn = warp >> 2;        // 4 M-warps x 3 N-warps
    int grp = lane >> 2, qk = lane & 3;
    int am = tid >> 1, ah = (tid & 1) * 16;   // A loader (tid < 256)

    for (int tile = blockIdx.x; tile < ntiles; tile += GEMM_GRID) {
        int row0 = tile << 7;

        float acc[2][10][4];
#pragma unroll
        for (int mt = 0; mt < 2; ++mt)
#pragma unroll
            for (int nt = 0; nt < 10; ++nt)
#pragma unroll
                for (int q = 0; q < 4; ++q) acc[mt][nt][q] = 0.f;

        auto load_stage = [&](int kt, int s) {
            int kg = kt * 32;
            if (tid < 256) {
                const float* ap = g_A + (size_t)(row0 + am) * K2 + kg + ah;
#pragma unroll
                for (int i = 0; i < 4; ++i)
                    cpasync16(&AS(s, am, ah + 4 * i), ap + 4 * i);
            }
#pragma unroll
            for (int i = 0; i < 5; ++i) {
                int idx = tid + 384 * i;              // < 1920
                int rowb = idx >> 3;
                int c4 = (idx & 7) << 2;
                cpasync16(&BS(s, rowb, c4), g_Wt + (size_t)rowb * K2 + kg + c4);
            }
            cp_commit();
        };

        __syncthreads();      // protect smem reuse across tiles
        load_stage(0, 0);

        for (int kt = 0; kt < 15; ++kt) {
            int s = kt & 1;
            if (kt < 14) {
                load_stage(kt + 1, s ^ 1);
                cp_wait<1>();
            } else {
                cp_wait<0>();
            }
            __syncthreads();

#pragma unroll
            for (int ks = 0; ks < 4; ++ks) {
                int k8 = ks * 8;
                uint32_t a[2][4], b[10][2];
#pragma unroll
                for (int mt = 0; mt < 2; ++mt) {
                    int r = wm * 32 + mt * 16 + grp;
                    a[mt][0] = __float_as_uint(AS(s, r, k8 + qk));
                    a[mt][1] = __float_as_uint(AS(s, r + 8, k8 + qk));
                    a[mt][2] = __float_as_uint(AS(s, r, k8 + qk + 4));
                    a[mt][3] = __float_as_uint(AS(s, r + 8, k8 + qk + 4));
                }
#pragma unroll
                for (int nt = 0; nt < 10; ++nt) {
                    int nc = wn * 80 + nt * 8 + grp;
                    b[nt][0] = __float_as_uint(BS(s, nc, k8 + qk));
                    b[nt][1] = __float_as_uint(BS(s, nc, k8 + qk + 4));
                }
#pragma unroll
                for (int mt = 0; mt < 2; ++mt)
#pragma unroll
                    for (int nt = 0; nt < 10; ++nt)
                        mma_tf32(acc[mt][nt], a[mt], b[nt]);
            }
            __syncthreads();
        }

        // epilogue: BN + swish -> compact g_Y[o][row]
#pragma unroll
        for (int mt = 0; mt < 2; ++mt) {
            int r0 = row0 + wm * 32 + mt * 16 + grp;
            int r1 = r0 + 8;
            bool v0 = r0 < nrows, v1 = r1 < nrows;
#pragma unroll
            for (int nt = 0; nt < 10; ++nt) {
                int ocl = wn * 80 + nt * 8 + 2 * qk;
#pragma unroll
                for (int h = 0; h < 2; ++h) {
                    int o = ocl + h;
                    float s = sc_s[o], off = sc_o[o];
                    size_t ocol = (size_t)o * MAXROWS;
                    if (v0) {
                        float y = acc[mt][nt][h] * s + off;
                        g_Y[ocol + r0] = y / (1.0f + expf(-y));
                    }
                    if (v1) {
                        float y = acc[mt][nt][2 + h] * s + off;
                        g_Y[ocol + r1] = y / (1.0f + expf(-y));
                    }
                }
            }
        }
    }
}

// ---------------- 6) final output: coalesced merge of g_Y + empty constants ----------------
__global__ void __launch_bounds__(256) write_out_kernel(
    const float* __restrict__ bias,
    const float* __restrict__ gamma,
    const float* __restrict__ beta,
    const float* __restrict__ bmean,
    const float* __restrict__ bvar,
    float* __restrict__ out)          // [B][240][V]
{
    __shared__ float s_empty[60];
    int t = threadIdx.x;
    int span = blockIdx.x;            // < B*V/1024
    int o0 = blockIdx.y * 60;
    int b = span >> 5;                // 32 spans per batch
    int v0 = (span & 31) << 10;

    if (t < 60) {
        int o = o0 + t;
        float s = gamma[o] * rsqrtf(bvar[o] + 1e-5f);
        float y = (bias[o] - bmean[o]) * s + beta[o];
        s_empty[t] = y / (1.0f + expf(-y));
    }
    int4 rows = *reinterpret_cast<const int4*>(g_vox2row + b * Vv + v0 + 4 * t);
    __syncthreads();

    size_t obase = (size_t)b * Cc * Vv + v0 + 4 * t;
    for (int j = 0; j < 60; ++j) {
        int o = o0 + j;
        float e = s_empty[j];
        const float* ycol = g_Y + (size_t)o * MAXROWS;
        float4 r;
        r.x = (rows.x >= 0) ? ycol[rows.x] : e;
        r.y = (rows.y >= 0) ? ycol[rows.y] : e;
        r.z = (rows.z >= 0) ? ycol[rows.z] : e;
        r.w = (rows.w >= 0) ? ycol[rows.w] : e;
        __stcs(reinterpret_cast<float4*>(out + obase + (size_t)o * Vv), r);
    }
}

// ---------------- launch ----------------
extern "C" void kernel_launch(void* const* d_in, const int* in_sizes, int n_in,
                              void* d_out, int out_size) {
    const float* features = (const float*)d_in[0];
    const float* coords   = (const float*)d_in[1];
    const float* conv_w   = (const float*)d_in[2];
    const float* conv_b   = (const float*)d_in[3];
    const float* bn_gamma = (const float*)d_in[4];
    const float* bn_beta  = (const float*)d_in[5];
    const float* bn_mean  = (const float*)d_in[6];
    const float* bn_var   = (const float*)d_in[7];

    float* out = (float*)d_out;                       // [B, C, R^3]
    float* nc_out = out + (size_t)Bn * Cc * Vv;       // [B, 3, N]

    cudaFuncSetAttribute(gemm_kernel, cudaFuncAttributeMaxDynamicSharedMemorySize, GEMM_SMEM);

    init_stats_kernel<<<264, 1024>>>(conv_w, coords);
    points_kernel<<<(Bn * Nn) / 256, 256>>>(coords, nc_out);
    scan1_kernel<<<1024, 256>>>();
    scan3_kernel<<<1024, 256>>>();
    gtrans_kernel<<<dim3(Nn / 128, 5, Bn), 256>>>(features);
    reduce_kernel<<<1024, 256>>>();
    gemm_kernel<<<GEMM_GRID, 384, GEMM_SMEM>>>(conv_b, bn_gamma, bn_beta,
                                               bn_mean, bn_var);
    write_out_kernel<<<dim3((Bn * Vv) / 1024, 4), 256>>>(conv_b, bn_gamma, bn_beta,
                                                         bn_mean, bn_var, out);
}

// round 15
// speedup vs baseline: 1.5621x; 1.1095x over previous
#include <cuda_runtime.h>
#include <cuda_fp16.h>
#include <cstdint>
#include <climits>
#include <cmath>

#define Bn 8
#define Cc 240
#define Nn 16384
#define Rr 32
#define Vv 32768              // R^3
#define K2 480                // 2*C
#define FSH 256               // padded row stride of g_featT (halfs)
#define MAXROWS (Bn * Nn)     // worst case (131072)

// ---------------- scratch (static device globals; no allocations) ----------------
__device__ __half g_featT[(size_t)Bn * Nn * FSH]; // CSR-ordered point features, fp16 [slot][256]
__device__ float g_A[(size_t)MAXROWS * K2];       // compact GEMM A (tf32-rounded)
__device__ float g_Y[(size_t)Cc * MAXROWS];       // compact GEMM result, column-major [o][row]
__device__ float g_Wt[Cc * K2];                   // tf32-rounded weights
__device__ int   g_cnt[Bn * Vv];
__device__ int   g_idx[Bn * Nn];                  // packed: idx (15b) | arrival (14b)
__device__ int   g_vox2row[Bn * Vv];              // -1 if empty
__device__ int   g_rowoff[MAXROWS];
__device__ int   g_rowcnt[MAXROWS];
__device__ unsigned long long g_bsum[1024];       // packed (rows<<32)|points per 256-voxel block
__device__ int   g_nrows;
__device__ float g_stats[Bn * 4];

__device__ __forceinline__ float tf32r(float x) {
    uint32_t u;
    asm("cvt.rna.tf32.f32 %0, %1;" : "=r"(u) : "f"(x));
    return __uint_as_float(u);
}

__device__ __forceinline__ void mma_tf32(float* c, const uint32_t* a, const uint32_t* b) {
    asm volatile(
        "mma.sync.aligned.m16n8k8.row.col.f32.tf32.tf32.f32 "
        "{%0,%1,%2,%3}, {%4,%5,%6,%7}, {%8,%9}, {%0,%1,%2,%3};"
        : "+f"(c[0]), "+f"(c[1]), "+f"(c[2]), "+f"(c[3])
        : "r"(a[0]), "r"(a[1]), "r"(a[2]), "r"(a[3]), "r"(b[0]), "r"(b[1]));
}

__device__ __forceinline__ void cpasync16(void* smem_ptr, const void* gptr) {
    unsigned s = (unsigned)__cvta_generic_to_shared(smem_ptr);
    asm volatile("cp.async.cg.shared.global [%0], [%1], 16;" :: "r"(s), "l"(gptr));
}
__device__ __forceinline__ void cp_commit() { asm volatile("cp.async.commit_group;"); }
template <int N>
__device__ __forceinline__ void cp_wait() { asm volatile("cp.async.wait_group %0;" :: "n"(N)); }

// ---------------- 0) fused: zero counters + tf32 W (blocks 0-255) | per-batch stats (256-263) ----
__global__ void __launch_bounds__(1024) init_stats_kernel(const float* __restrict__ W,
                                                          const float* __restrict__ coords) {
    int t = threadIdx.x;
    if (blockIdx.x < 256) {
        int i = blockIdx.x * 1024 + t;                // < B*V
        g_cnt[i] = 0;
        g_vox2row[i] = -1;
        if (i < Cc * K2) g_Wt[i] = tf32r(W[i]);
        return;
    }
    // ---- stats for batch b ----
    int b = blockIdx.x - 256;
    __shared__ float wsm[96];
    __shared__ float smean[3];
    int lane = t & 31, w = t >> 5;
    const float* cx = coords + (size_t)b * 3 * Nn;
    float sx = 0.f, sy = 0.f, sz = 0.f;
    for (int n = t; n < Nn; n += 1024) {
        sx += cx[n];
        sy += cx[Nn + n];
        sz += cx[2 * Nn + n];
    }
#pragma unroll
    for (int d = 16; d; d >>= 1) {
        sx += __shfl_down_sync(0xffffffffu, sx, d);
        sy += __shfl_down_sync(0xffffffffu, sy, d);
        sz += __shfl_down_sync(0xffffffffu, sz, d);
    }
    if (lane == 0) { wsm[w] = sx; wsm[32 + w] = sy; wsm[64 + w] = sz; }
    __syncthreads();
    if (w == 0) {
        float a = wsm[lane], bb = wsm[32 + lane], c = wsm[64 + lane];
#pragma unroll
        for (int d = 16; d; d >>= 1) {
            a += __shfl_down_sync(0xffffffffu, a, d);
            bb += __shfl_down_sync(0xffffffffu, bb, d);
            c += __shfl_down_sync(0xffffffffu, c, d);
        }
        if (lane == 0) {
            smean[0] = a / (float)Nn;
            smean[1] = bb / (float)Nn;
            smean[2] = c / (float)Nn;
        }
    }
    __syncthreads();
    float mx = smean[0], my = smean[1], mz = smean[2];
    float mn = 0.f;
    for (int n = t; n < Nn; n += 1024) {
        float x = cx[n] - mx, y = cx[Nn + n] - my, z = cx[2 * Nn + n] - mz;
        mn = fmaxf(mn, sqrtf(x * x + y * y + z * z));
    }
#pragma unroll
    for (int d = 16; d; d >>= 1) mn = fmaxf(mn, __shfl_down_sync(0xffffffffu, mn, d));
    if (lane == 0) wsm[w] = mn;
    __syncthreads();
    if (w == 0) {
        float a = wsm[lane];
#pragma unroll
        for (int d = 16; d; d >>= 1) a = fmaxf(a, __shfl_down_sync(0xffffffffu, a, d));
        if (lane == 0) {
            g_stats[b * 4 + 0] = mx;
            g_stats[b * 4 + 1] = my;
            g_stats[b * 4 + 2] = mz;
            g_stats[b * 4 + 3] = a * 2.0f;   // denom (EPS = 0)
        }
    }
}

// ---------------- 1) normalized coords + packed voxel idx/arrival + counts ----------------
__global__ void points_kernel(const float* __restrict__ coords, float* __restrict__ nc_out) {
    int i = blockIdx.x * blockDim.x + threadIdx.x;   // < B*N
    int b = i >> 14;
    int n = i & (Nn - 1);
    float mx = g_stats[b * 4 + 0], my = g_stats[b * 4 + 1];
    float mz = g_stats[b * 4 + 2], dn = g_stats[b * 4 + 3];
    const float* cb = coords + (size_t)b * 3 * Nn;
    float x = cb[n], y = cb[Nn + n], z = cb[2 * Nn + n];

    float ncx = ((x - mx) / dn + 0.5f) * (float)Rr;
    float ncy = ((y - my) / dn + 0.5f) * (float)Rr;
    float ncz = ((z - mz) / dn + 0.5f) * (float)Rr;
    ncx = fminf(fmaxf(ncx, 0.f), (float)(Rr - 1));
    ncy = fminf(fmaxf(ncy, 0.f), (float)(Rr - 1));
    ncz = fminf(fmaxf(ncz, 0.f), (float)(Rr - 1));

    float* nb = nc_out + (size_t)b * 3 * Nn;
    nb[n] = ncx;
    nb[Nn + n] = ncy;
    nb[2 * Nn + n] = ncz;

    int vx = (int)rintf(ncx);   // round-half-even == jnp.round
    int vy = (int)rintf(ncy);
    int vz = (int)rintf(ncz);
    int idx = vx * (Rr * Rr) + vy * Rr + vz;
    int arr = atomicAdd(&g_cnt[b * Vv + idx], 1);    // arrival index (order-independent content)
    g_idx[i] = idx | (arr << 15);
}

// ---------------- 2a) block totals (256 voxels/block) ----------------
__global__ void scan1_kernel() {
    int blk = blockIdx.x, t = threadIdx.x;
    int cnt = g_cnt[blk * 256 + t];
    unsigned long long v = ((unsigned long long)(cnt > 0) << 32) | (unsigned)cnt;
#pragma unroll
    for (int d = 16; d; d >>= 1) v += __shfl_down_sync(0xffffffffu, v, d);
    __shared__ unsigned long long w[8];
    if ((t & 31) == 0) w[t >> 5] = v;
    __syncthreads();
    if (t == 0) {
        unsigned long long s = 0;
#pragma unroll
        for (int i = 0; i < 8; ++i) s += w[i];
        g_bsum[blk] = s;
    }
}

// ---------------- 2b) rows+offsets: every block redundantly scans the 1024 bsums ----------------
__global__ void scan3_kernel() {
    int blk = blockIdx.x, t = threadIdx.x, lane = t & 31, w = t >> 5;

    __shared__ unsigned long long part[256];
    {
        const unsigned long long* bs = g_bsum + 4 * t;
        part[t] = bs[0] + bs[1] + bs[2] + bs[3];
    }
    __syncthreads();
    unsigned long long x = part[t];
#pragma unroll
    for (int d = 1; d < 32; d <<= 1) {
        unsigned long long y = __shfl_up_sync(0xffffffffu, x, d);
        if (lane >= d) x += y;
    }
    __shared__ unsigned long long wsum[8];
    if (lane == 31) wsum[w] = x;
    __syncthreads();
    __shared__ unsigned long long wexc[8];
    if (t < 8) {
        unsigned long long s = 0;
        for (int i = 0; i < t; ++i) s += wsum[i];
        wexc[t] = s;
    }
    __syncthreads();
    __shared__ unsigned long long s_base, s_total;
    if (t == (blk >> 2)) {
        unsigned long long excl_chunk = x - part[t] + wexc[w];
        const unsigned long long* bs = g_bsum + (blk & ~3);
        for (int i = 0; i < (blk & 3); ++i) excl_chunk += bs[i];
        s_base = excl_chunk;
    }
    if (t == 255) s_total = x + wexc[7];
    __syncthreads();
    if (blk == 0 && t == 0) g_nrows = (int)(s_total >> 32);

    int bv = blk * 256 + t;
    int cnt = g_cnt[bv];
    unsigned long long v = ((unsigned long long)(cnt > 0) << 32) | (unsigned)cnt;
    unsigned long long orig = v;
#pragma unroll
    for (int d = 1; d < 32; d <<= 1) {
        unsigned long long y = __shfl_up_sync(0xffffffffu, v, d);
        if (lane >= d) v += y;
    }
    __syncthreads();
    if (lane == 31) wsum[w] = v;
    __syncthreads();
    if (t < 8) {
        unsigned long long s = 0;
        for (int i = 0; i < t; ++i) s += wsum[i];
        wexc[t] = s;
    }
    __syncthreads();
    unsigned long long excl = v - orig + wexc[w] + s_base;
    if (cnt > 0) {
        int row = (int)(excl >> 32);
        int off = (int)(excl & 0xffffffffu);
        g_vox2row[bv] = row;
        g_rowcnt[row] = cnt;
        g_rowoff[row] = off;
    }
}

// ---------------- 3) gather-transpose -> fp16 CSR rows; coalesced stores + smem swizzle ------
__global__ void __launch_bounds__(256) gtrans_kernel(const float* __restrict__ f) {
    __shared__ float4 sm4[48][32];
    __shared__ int s_slot[128];
    int b = blockIdx.z;
    int n0 = blockIdx.x << 7;
    int c0 = blockIdx.y * 48;
    int t = threadIdx.x;

    if (t < 128) {
        int pk = g_idx[(b << 14) + n0 + t];
        int idx = pk & 0x7fff;
        int row = g_vox2row[b * Vv + idx];
        s_slot[t] = g_rowoff[row] + (pk >> 15);
    }

    int col4 = t & 31, r0 = t >> 5;
#pragma unroll
    for (int rr = 0; rr < 6; ++rr) {
        int r = r0 + rr * 8;
        float4 v = __ldcs(reinterpret_cast<const float4*>(
            f + ((size_t)b * Cc + c0 + r) * Nn + n0 + col4 * 4));
        sm4[r][(col4 + r + (r >> 2)) & 31] = v;
    }
    __syncthreads();

    const float* smf = reinterpret_cast<const float*>(sm4);
#pragma unroll
    for (int it = 0; it < 6; ++it) {
        int w = it * 256 + t;
        int j = w % 12;
        int p = w / 12;
        int pq = p >> 2, pk = p & 3;
        float o[4];
#pragma unroll
        for (int kk = 0; kk < 4; ++kk) {
            int r = 4 * j + kk;
            o[kk] = smf[r * 128 + (((pq + r + (r >> 2)) & 31) << 2) + pk];
        }
        __half2 h0 = __floats2half2_rn(o[0], o[1]);
        __half2 h1 = __floats2half2_rn(o[2], o[3]);
        uint2 pk2 = make_uint2(*reinterpret_cast<uint32_t*>(&h0),
                               *reinterpret_cast<uint32_t*>(&h1));
        *reinterpret_cast<uint2*>(
            reinterpret_cast<char*>(g_featT) + ((size_t)s_slot[p] * FSH + c0 + 4 * j) * 2) = pk2;
    }
}

// ---------------- 4) reduce: 8 row-groups per 256-block, fp16 CSR rows -> tf32 A --------------
__global__ void __launch_bounds__(256) reduce_kernel() {
    int nrows = g_nrows;
    int t = threadIdx.x & 31;            // lane within group (use 30)
    int grpi = threadIdx.x >> 5;         // 0..7
    if (t >= 30) return;
    for (int row = blockIdx.x * 8 + grpi; row < nrows; row += gridDim.x * 8) {
        int cnt = g_rowcnt[row];
        int off = g_rowoff[row];
        const uint4* base = reinterpret_cast<const uint4*>(
            reinterpret_cast<const char*>(g_featT) + ((size_t)off * FSH + 8 * t) * 2);
        float s[8], m[8];
#pragma unroll
        for (int c = 0; c < 8; ++c) { s[c] = 0.f; m[c] = -INFINITY; }
        for (int p = 0; p < cnt; ++p) {
            uint4 v = __ldcs(base + (size_t)p * (FSH / 8));
            uint32_t uu[4] = {v.x, v.y, v.z, v.w};
#pragma unroll
            for (int q = 0; q < 4; ++q) {
                float2 f2 = __half22float2(*reinterpret_cast<__half2*>(&uu[q]));
                m[2 * q]     = fmaxf(m[2 * q], f2.x);     s[2 * q]     += f2.x;
                m[2 * q + 1] = fmaxf(m[2 * q + 1], f2.y); s[2 * q + 1] += f2.y;
            }
        }
        float inv = 1.0f / (float)cnt;
        float* arow = g_A + (size_t)row * K2;
        *reinterpret_cast<float4*>(arow + 8 * t) =
            make_float4(tf32r(m[0]), tf32r(m[1]), tf32r(m[2]), tf32r(m[3]));
        *reinterpret_cast<float4*>(arow + 8 * t + 4) =
            make_float4(tf32r(m[4]), tf32r(m[5]), tf32r(m[6]), tf32r(m[7]));
        *reinterpret_cast<float4*>(arow + Cc + 8 * t) =
            make_float4(tf32r(s[0] * inv), tf32r(s[1] * inv), tf32r(s[2] * inv), tf32r(s[3] * inv));
        *reinterpret_cast<float4*>(arow + Cc + 8 * t + 4) =
            make_float4(tf32r(s[4] * inv), tf32r(s[5] * inv), tf32r(s[6] * inv), tf32r(s[7] * inv));
    }
}

// ---------------- 5) tf32 GEMM single-pass N=240, persistent grid -> g_Y[o][row] ----------------
// BM=128, BN=240, BK=32; 384 threads = 12 warps (4M x 3N); warp tile 32x80.
#define AS(s, r, k) As[(((s) * 128 + (r)) * 36) + (k)]
#define BS(s, r, k) Bsm[(((s) * 240 + (r)) * 36) + (k)]
#define GEMM_SMEM ((2 * 128 * 36 + 2 * 240 * 36 + 2 * 240) * 4)
#define GEMM_GRID 296

__global__ void __launch_bounds__(384) gemm_kernel(
    const float* __restrict__ bias,
    const float* __restrict__ gamma,
    const float* __restrict__ beta,
    const float* __restrict__ bmean,
    const float* __restrict__ bvar)
{
    int nrows = g_nrows;
    int ntiles = (nrows + 127) >> 7;

    extern __shared__ float dsm[];
    float* As  = dsm;                       // [2][128][36]
    float* Bsm = dsm + 2 * 128 * 36;        // [2][240][36]
    float* sc_s = Bsm + 2 * 240 * 36;       // [240]
    float* sc_o = sc_s + 240;

    int tid = threadIdx.x;

    if (tid < 240) {
        float s = gamma[tid] * rsqrtf(bvar[tid] + 1e-5f);
        sc_s[tid] = s;
        sc_o[tid] = (bias[tid] - bmean[tid]) * s + beta[tid];
    }

    int lane = tid & 31, warp = tid >> 5;
    int wm = warp & 3, wn = warp >> 2;        // 4 M-warps x 3 N-warps
    int grp = lane >> 2, qk = lane & 3;
    int am = tid >> 1, ah = (tid & 1) * 16;   // A loader (tid < 256)

    for (int tile = blockIdx.x; tile < ntiles; tile += GEMM_GRID) {
        int row0 = tile << 7;

        float acc[2][10][4];
#pragma unroll
        for (int mt = 0; mt < 2; ++mt)
#pragma unroll
            for (int nt = 0; nt < 10; ++nt)
#pragma unroll
                for (int q = 0; q < 4; ++q) acc[mt][nt][q] = 0.f;

        auto load_stage = [&](int kt, int s) {
            int kg = kt * 32;
            if (tid < 256) {
                const float* ap = g_A + (size_t)(row0 + am) * K2 + kg + ah;
#pragma unroll
                for (int i = 0; i < 4; ++i)
                    cpasync16(&AS(s, am, ah + 4 * i), ap + 4 * i);
            }
#pragma unroll
            for (int i = 0; i < 5; ++i) {
                int idx = tid + 384 * i;              // < 1920
                int rowb = idx >> 3;
                int c4 = (idx & 7) << 2;
                cpasync16(&BS(s, rowb, c4), g_Wt + (size_t)rowb * K2 + kg + c4);
            }
            cp_commit();
        };

        __syncthreads();      // protect smem reuse across tiles
        load_stage(0, 0);

        for (int kt = 0; kt < 15; ++kt) {
            int s = kt & 1;
            if (kt < 14) {
                load_stage(kt + 1, s ^ 1);
                cp_wait<1>();
            } else {
                cp_wait<0>();
            }
            __syncthreads();

#pragma unroll
            for (int ks = 0; ks < 4; ++ks) {
                int k8 = ks * 8;
                uint32_t a[2][4], b[10][2];
#pragma unroll
                for (int mt = 0; mt < 2; ++mt) {
                    int r = wm * 32 + mt * 16 + grp;
                    a[mt][0] = __float_as_uint(AS(s, r, k8 + qk));
                    a[mt][1] = __float_as_uint(AS(s, r + 8, k8 + qk));
                    a[mt][2] = __float_as_uint(AS(s, r, k8 + qk + 4));
                    a[mt][3] = __float_as_uint(AS(s, r + 8, k8 + qk + 4));
                }
#pragma unroll
                for (int nt = 0; nt < 10; ++nt) {
                    int nc = wn * 80 + nt * 8 + grp;
                    b[nt][0] = __float_as_uint(BS(s, nc, k8 + qk));
                    b[nt][1] = __float_as_uint(BS(s, nc, k8 + qk + 4));
                }
#pragma unroll
                for (int mt = 0; mt < 2; ++mt)
#pragma unroll
                    for (int nt = 0; nt < 10; ++nt)
                        mma_tf32(acc[mt][nt], a[mt], b[nt]);
            }
            __syncthreads();
        }

        // epilogue: BN + swish -> compact g_Y[o][row]
#pragma unroll
        for (int mt = 0; mt < 2; ++mt) {
            int r0 = row0 + wm * 32 + mt * 16 + grp;
            int r1 = r0 + 8;
            bool v0 = r0 < nrows, v1 = r1 < nrows;
#pragma unroll
            for (int nt = 0; nt < 10; ++nt) {
                int ocl = wn * 80 + nt * 8 + 2 * qk;
#pragma unroll
                for (int h = 0; h < 2; ++h) {
                    int o = ocl + h;
                    float s = sc_s[o], off = sc_o[o];
                    size_t ocol = (size_t)o * MAXROWS;
                    if (v0) {
                        float y = acc[mt][nt][h] * s + off;
                        g_Y[ocol + r0] = y / (1.0f + expf(-y));
                    }
                    if (v1) {
                        float y = acc[mt][nt][2 + h] * s + off;
                        g_Y[ocol + r1] = y / (1.0f + expf(-y));
                    }
                }
            }
        }
    }
}

// ---------------- 6) final output: coalesced merge of g_Y + empty constants ----------------
__global__ void __launch_bounds__(256) write_out_kernel(
    const float* __restrict__ bias,
    const float* __restrict__ gamma,
    const float* __restrict__ beta,
    const float* __restrict__ bmean,
    const float* __restrict__ bvar,
    float* __restrict__ out)          // [B][240][V]
{
    __shared__ float s_empty[60];
    int t = threadIdx.x;
    int span = blockIdx.x;            // < B*V/1024
    int o0 = blockIdx.y * 60;
    int b = span >> 5;                // 32 spans per batch
    int v0 = (span & 31) << 10;

    if (t < 60) {
        int o = o0 + t;
        float s = gamma[o] * rsqrtf(bvar[o] + 1e-5f);
        float y = (bias[o] - bmean[o]) * s + beta[o];
        s_empty[t] = y / (1.0f + expf(-y));
    }
    int4 rows = *reinterpret_cast<const int4*>(g_vox2row + b * Vv + v0 + 4 * t);
    __syncthreads();

    size_t obase = (size_t)b * Cc * Vv + v0 + 4 * t;
    for (int j = 0; j < 60; ++j) {
        int o = o0 + j;
        float e = s_empty[j];
        const float* ycol = g_Y + (size_t)o * MAXROWS;
        float4 r;
        r.x = (rows.x >= 0) ? ycol[rows.x] : e;
        r.y = (rows.y >= 0) ? ycol[rows.y] : e;
        r.z = (rows.z >= 0) ? ycol[rows.z] : e;
        r.w = (rows.w >= 0) ? ycol[rows.w] : e;
        __stcs(reinterpret_cast<float4*>(out + obase + (size_t)o * Vv), r);
    }
}

// ---------------- launch ----------------
extern "C" void kernel_launch(void* const* d_in, const int* in_sizes, int n_in,
                              void* d_out, int out_size) {
    const float* features = (const float*)d_in[0];
    const float* coords   = (const float*)d_in[1];
    const float* conv_w   = (const float*)d_in[2];
    const float* conv_b   = (const float*)d_in[3];
    const float* bn_gamma = (const float*)d_in[4];
    const float* bn_beta  = (const float*)d_in[5];
    const float* bn_mean  = (const float*)d_in[6];
    const float* bn_var   = (const float*)d_in[7];

    float* out = (float*)d_out;                       // [B, C, R^3]
    float* nc_out = out + (size_t)Bn * Cc * Vv;       // [B, 3, N]

    cudaFuncSetAttribute(gemm_kernel, cudaFuncAttributeMaxDynamicSharedMemorySize, GEMM_SMEM);

    init_stats_kernel<<<264, 1024>>>(conv_w, coords);
    points_kernel<<<(Bn * Nn) / 256, 256>>>(coords, nc_out);
    scan1_kernel<<<1024, 256>>>();
    scan3_kernel<<<1024, 256>>>();
    gtrans_kernel<<<dim3(Nn / 128, 5, Bn), 256>>>(features);
    reduce_kernel<<<1024, 256>>>();
    gemm_kernel<<<GEMM_GRID, 384, GEMM_SMEM>>>(conv_b, bn_gamma, bn_beta,
                                               bn_mean, bn_var);
    write_out_kernel<<<dim3((Bn * Vv) / 1024, 4), 256>>>(conv_b, bn_gamma, bn_beta,
                                                         bn_mean, bn_var, out);
}

// round 16
// speedup vs baseline: 1.8340x; 1.1741x over previous
#include <cuda_runtime.h>
#include <cuda_fp16.h>
#include <cstdint>
#include <climits>
#include <cmath>

#define Bn 8
#define Cc 240
#define Nn 16384
#define Rr 32
#define Vv 32768              // R^3
#define K2 480                // 2*C
#define FSH 256               // padded row stride of g_featT (halfs)
#define MAXROWS (Bn * Nn)     // worst case (131072)

// ---------------- scratch (static device globals; no allocations) ----------------
__device__ __half g_featT[(size_t)Bn * Nn * FSH]; // CSR-ordered point features, fp16 [slot][256]
__device__ __half g_A[(size_t)MAXROWS * K2];      // compact GEMM A, fp16 [row][max240|avg240]
__device__ float  g_Y[(size_t)Cc * MAXROWS];      // compact GEMM result, column-major [o][row]
__device__ __half g_Wt[Cc * K2];                  // fp16 weights
__device__ int   g_cnt[Bn * Vv];
__device__ int   g_idx[Bn * Nn];                  // packed: idx (15b) | arrival (14b)
__device__ int   g_vox2row[Bn * Vv];              // -1 if empty
__device__ int   g_rowoff[MAXROWS];
__device__ int   g_rowcnt[MAXROWS];
__device__ unsigned long long g_bsum[1024];       // packed (rows<<32)|points per 256-voxel block
__device__ int   g_nrows;
__device__ float g_stats[Bn * 4];

__device__ __forceinline__ void mma_f16(float* c, const uint32_t* a, const uint32_t* b) {
    asm volatile(
        "mma.sync.aligned.m16n8k16.row.col.f32.f16.f16.f32 "
        "{%0,%1,%2,%3}, {%4,%5,%6,%7}, {%8,%9}, {%0,%1,%2,%3};"
        : "+f"(c[0]), "+f"(c[1]), "+f"(c[2]), "+f"(c[3])
        : "r"(a[0]), "r"(a[1]), "r"(a[2]), "r"(a[3]), "r"(b[0]), "r"(b[1]));
}

__device__ __forceinline__ void cpasync16(void* smem_ptr, const void* gptr) {
    unsigned s = (unsigned)__cvta_generic_to_shared(smem_ptr);
    asm volatile("cp.async.cg.shared.global [%0], [%1], 16;" :: "r"(s), "l"(gptr));
}
__device__ __forceinline__ void cp_commit() { asm volatile("cp.async.commit_group;"); }
template <int N>
__device__ __forceinline__ void cp_wait() { asm volatile("cp.async.wait_group %0;" :: "n"(N)); }

// ---------------- 0) fused: zero counters + fp16 W (blocks 0-255) | per-batch stats (256-263) ----
__global__ void __launch_bounds__(1024) init_stats_kernel(const float* __restrict__ W,
                                                          const float* __restrict__ coords) {
    int t = threadIdx.x;
    if (blockIdx.x < 256) {
        int i = blockIdx.x * 1024 + t;                // < B*V
        g_cnt[i] = 0;
        g_vox2row[i] = -1;
        if (i < Cc * K2) g_Wt[i] = __float2half_rn(W[i]);
        return;
    }
    // ---- stats for batch b ----
    int b = blockIdx.x - 256;
    __shared__ float wsm[96];
    __shared__ float smean[3];
    int lane = t & 31, w = t >> 5;
    const float* cx = coords + (size_t)b * 3 * Nn;
    float sx = 0.f, sy = 0.f, sz = 0.f;
    for (int n = t; n < Nn; n += 1024) {
        sx += cx[n];
        sy += cx[Nn + n];
        sz += cx[2 * Nn + n];
    }
#pragma unroll
    for (int d = 16; d; d >>= 1) {
        sx += __shfl_down_sync(0xffffffffu, sx, d);
        sy += __shfl_down_sync(0xffffffffu, sy, d);
        sz += __shfl_down_sync(0xffffffffu, sz, d);
    }
    if (lane == 0) { wsm[w] = sx; wsm[32 + w] = sy; wsm[64 + w] = sz; }
    __syncthreads();
    if (w == 0) {
        float a = wsm[lane], bb = wsm[32 + lane], c = wsm[64 + lane];
#pragma unroll
        for (int d = 16; d; d >>= 1) {
            a += __shfl_down_sync(0xffffffffu, a, d);
            bb += __shfl_down_sync(0xffffffffu, bb, d);
            c += __shfl_down_sync(0xffffffffu, c, d);
        }
        if (lane == 0) {
            smean[0] = a / (float)Nn;
            smean[1] = bb / (float)Nn;
            smean[2] = c / (float)Nn;
        }
    }
    __syncthreads();
    float mx = smean[0], my = smean[1], mz = smean[2];
    float mn = 0.f;
    for (int n = t; n < Nn; n += 1024) {
        float x = cx[n] - mx, y = cx[Nn + n] - my, z = cx[2 * Nn + n] - mz;
        mn = fmaxf(mn, sqrtf(x * x + y * y + z * z));
    }
#pragma unroll
    for (int d = 16; d; d >>= 1) mn = fmaxf(mn, __shfl_down_sync(0xffffffffu, mn, d));
    if (lane == 0) wsm[w] = mn;
    __syncthreads();
    if (w == 0) {
        float a = wsm[lane];
#pragma unroll
        for (int d = 16; d; d >>= 1) a = fmaxf(a, __shfl_down_sync(0xffffffffu, a, d));
        if (lane == 0) {
            g_stats[b * 4 + 0] = mx;
            g_stats[b * 4 + 1] = my;
            g_stats[b * 4 + 2] = mz;
            g_stats[b * 4 + 3] = a * 2.0f;   // denom (EPS = 0)
        }
    }
}

// ---------------- 1) normalized coords + packed voxel idx/arrival + counts ----------------
__global__ void points_kernel(const float* __restrict__ coords, float* __restrict__ nc_out) {
    int i = blockIdx.x * blockDim.x + threadIdx.x;   // < B*N
    int b = i >> 14;
    int n = i & (Nn - 1);
    float mx = g_stats[b * 4 + 0], my = g_stats[b * 4 + 1];
    float mz = g_stats[b * 4 + 2], dn = g_stats[b * 4 + 3];
    const float* cb = coords + (size_t)b * 3 * Nn;
    float x = cb[n], y = cb[Nn + n], z = cb[2 * Nn + n];

    float ncx = ((x - mx) / dn + 0.5f) * (float)Rr;
    float ncy = ((y - my) / dn + 0.5f) * (float)Rr;
    float ncz = ((z - mz) / dn + 0.5f) * (float)Rr;
    ncx = fminf(fmaxf(ncx, 0.f), (float)(Rr - 1));
    ncy = fminf(fmaxf(ncy, 0.f), (float)(Rr - 1));
    ncz = fminf(fmaxf(ncz, 0.f), (float)(Rr - 1));

    float* nb = nc_out + (size_t)b * 3 * Nn;
    nb[n] = ncx;
    nb[Nn + n] = ncy;
    nb[2 * Nn + n] = ncz;

    int vx = (int)rintf(ncx);   // round-half-even == jnp.round
    int vy = (int)rintf(ncy);
    int vz = (int)rintf(ncz);
    int idx = vx * (Rr * Rr) + vy * Rr + vz;
    int arr = atomicAdd(&g_cnt[b * Vv + idx], 1);    // arrival index (order-independent content)
    g_idx[i] = idx | (arr << 15);
}

// ---------------- 2a) block totals (256 voxels/block) ----------------
__global__ void scan1_kernel() {
    int blk = blockIdx.x, t = threadIdx.x;
    int cnt = g_cnt[blk * 256 + t];
    unsigned long long v = ((unsigned long long)(cnt > 0) << 32) | (unsigned)cnt;
#pragma unroll
    for (int d = 16; d; d >>= 1) v += __shfl_down_sync(0xffffffffu, v, d);
    __shared__ unsigned long long w[8];
    if ((t & 31) == 0) w[t >> 5] = v;
    __syncthreads();
    if (t == 0) {
        unsigned long long s = 0;
#pragma unroll
        for (int i = 0; i < 8; ++i) s += w[i];
        g_bsum[blk] = s;
    }
}

// ---------------- 2b) rows+offsets: every block redundantly scans the 1024 bsums ----------------
__global__ void scan3_kernel() {
    int blk = blockIdx.x, t = threadIdx.x, lane = t & 31, w = t >> 5;

    __shared__ unsigned long long part[256];
    {
        const unsigned long long* bs = g_bsum + 4 * t;
        part[t] = bs[0] + bs[1] + bs[2] + bs[3];
    }
    __syncthreads();
    unsigned long long x = part[t];
#pragma unroll
    for (int d = 1; d < 32; d <<= 1) {
        unsigned long long y = __shfl_up_sync(0xffffffffu, x, d);
        if (lane >= d) x += y;
    }
    __shared__ unsigned long long wsum[8];
    if (lane == 31) wsum[w] = x;
    __syncthreads();
    __shared__ unsigned long long wexc[8];
    if (t < 8) {
        unsigned long long s = 0;
        for (int i = 0; i < t; ++i) s += wsum[i];
        wexc[t] = s;
    }
    __syncthreads();
    __shared__ unsigned long long s_base, s_total;
    if (t == (blk >> 2)) {
        unsigned long long excl_chunk = x - part[t] + wexc[w];
        const unsigned long long* bs = g_bsum + (blk & ~3);
        for (int i = 0; i < (blk & 3); ++i) excl_chunk += bs[i];
        s_base = excl_chunk;
    }
    if (t == 255) s_total = x + wexc[7];
    __syncthreads();
    if (blk == 0 && t == 0) g_nrows = (int)(s_total >> 32);

    int bv = blk * 256 + t;
    int cnt = g_cnt[bv];
    unsigned long long v = ((unsigned long long)(cnt > 0) << 32) | (unsigned)cnt;
    unsigned long long orig = v;
#pragma unroll
    for (int d = 1; d < 32; d <<= 1) {
        unsigned long long y = __shfl_up_sync(0xffffffffu, v, d);
        if (lane >= d) v += y;
    }
    __syncthreads();
    if (lane == 31) wsum[w] = v;
    __syncthreads();
    if (t < 8) {
        unsigned long long s = 0;
        for (int i = 0; i < t; ++i) s += wsum[i];
        wexc[t] = s;
    }
    __syncthreads();
    unsigned long long excl = v - orig + wexc[w] + s_base;
    if (cnt > 0) {
        int row = (int)(excl >> 32);
        int off = (int)(excl & 0xffffffffu);
        g_vox2row[bv] = row;
        g_rowcnt[row] = cnt;
        g_rowoff[row] = off;
    }
}

// ---------------- 3) gather-transpose -> fp16 CSR rows; coalesced stores + smem swizzle ------
__global__ void __launch_bounds__(256) gtrans_kernel(const float* __restrict__ f) {
    __shared__ float4 sm4[48][32];
    __shared__ int s_slot[128];
    int b = blockIdx.z;
    int n0 = blockIdx.x << 7;
    int c0 = blockIdx.y * 48;
    int t = threadIdx.x;

    if (t < 128) {
        int pk = g_idx[(b << 14) + n0 + t];
        int idx = pk & 0x7fff;
        int row = g_vox2row[b * Vv + idx];
        s_slot[t] = g_rowoff[row] + (pk >> 15);
    }

    int col4 = t & 31, r0 = t >> 5;
#pragma unroll
    for (int rr = 0; rr < 6; ++rr) {
        int r = r0 + rr * 8;
        float4 v = __ldcs(reinterpret_cast<const float4*>(
            f + ((size_t)b * Cc + c0 + r) * Nn + n0 + col4 * 4));
        sm4[r][(col4 + r + (r >> 2)) & 31] = v;
    }
    __syncthreads();

    const float* smf = reinterpret_cast<const float*>(sm4);
#pragma unroll
    for (int it = 0; it < 6; ++it) {
        int w = it * 256 + t;
        int j = w % 12;
        int p = w / 12;
        int pq = p >> 2, pk = p & 3;
        float o[4];
#pragma unroll
        for (int kk = 0; kk < 4; ++kk) {
            int r = 4 * j + kk;
            o[kk] = smf[r * 128 + (((pq + r + (r >> 2)) & 31) << 2) + pk];
        }
        __half2 h0 = __floats2half2_rn(o[0], o[1]);
        __half2 h1 = __floats2half2_rn(o[2], o[3]);
        uint2 pk2 = make_uint2(*reinterpret_cast<uint32_t*>(&h0),
                               *reinterpret_cast<uint32_t*>(&h1));
        *reinterpret_cast<uint2*>(
            reinterpret_cast<char*>(g_featT) + ((size_t)s_slot[p] * FSH + c0 + 4 * j) * 2) = pk2;
    }
}

// ---------------- 4) reduce: 8 row-groups per 256-block, fp16 CSR rows -> fp16 A --------------
__global__ void __launch_bounds__(256) reduce_kernel() {
    int nrows = g_nrows;
    int t = threadIdx.x & 31;            // lane within group (use 30)
    int grpi = threadIdx.x >> 5;         // 0..7
    if (t >= 30) return;
    for (int row = blockIdx.x * 8 + grpi; row < nrows; row += gridDim.x * 8) {
        int cnt = g_rowcnt[row];
        int off = g_rowoff[row];
        const uint4* base = reinterpret_cast<const uint4*>(
            reinterpret_cast<const char*>(g_featT) + ((size_t)off * FSH + 8 * t) * 2);
        float s[8], m[8];
#pragma unroll
        for (int c = 0; c < 8; ++c) { s[c] = 0.f; m[c] = -INFINITY; }
        for (int p = 0; p < cnt; ++p) {
            uint4 v = __ldcs(base + (size_t)p * (FSH / 8));
            uint32_t uu[4] = {v.x, v.y, v.z, v.w};
#pragma unroll
            for (int q = 0; q < 4; ++q) {
                float2 f2 = __half22float2(*reinterpret_cast<__half2*>(&uu[q]));
                m[2 * q]     = fmaxf(m[2 * q], f2.x);     s[2 * q]     += f2.x;
                m[2 * q + 1] = fmaxf(m[2 * q + 1], f2.y); s[2 * q + 1] += f2.y;
            }
        }
        float inv = 1.0f / (float)cnt;
        __half* arow = g_A + (size_t)row * K2;
        uint2 mp, ap;
        {
            __half2 h0 = __floats2half2_rn(m[0], m[1]);
            __half2 h1 = __floats2half2_rn(m[2], m[3]);
            mp = make_uint2(*reinterpret_cast<uint32_t*>(&h0), *reinterpret_cast<uint32_t*>(&h1));
            *reinterpret_cast<uint2*>(arow + 8 * t) = mp;
            h0 = __floats2half2_rn(m[4], m[5]);
            h1 = __floats2half2_rn(m[6], m[7]);
            mp = make_uint2(*reinterpret_cast<uint32_t*>(&h0), *reinterpret_cast<uint32_t*>(&h1));
            *reinterpret_cast<uint2*>(arow + 8 * t + 4) = mp;
            h0 = __floats2half2_rn(s[0] * inv, s[1] * inv);
            h1 = __floats2half2_rn(s[2] * inv, s[3] * inv);
            ap = make_uint2(*reinterpret_cast<uint32_t*>(&h0), *reinterpret_cast<uint32_t*>(&h1));
            *reinterpret_cast<uint2*>(arow + Cc + 8 * t) = ap;
            h0 = __floats2half2_rn(s[4] * inv, s[5] * inv);
            h1 = __floats2half2_rn(s[6] * inv, s[7] * inv);
            ap = make_uint2(*reinterpret_cast<uint32_t*>(&h0), *reinterpret_cast<uint32_t*>(&h1));
            *reinterpret_cast<uint2*>(arow + Cc + 8 * t + 4) = ap;
        }
    }
}

// ---------------- 5) fp16 GEMM (m16n8k16) single-pass N=240, persistent -> g_Y[o][row] --------
// BM=128, BN=240, BK=32; 384 threads = 12 warps (4M x 3N); warp tile 32x80.
// Smem stride 40 halfs -> fragment half2 loads hit bank (20r+qk+c)%32, all lanes distinct.
#define ASH(s, r, k) Ash[(((s) * 128 + (r)) * 40) + (k)]
#define BSH(s, r, k) Bsh[(((s) * 240 + (r)) * 40) + (k)]
#define GEMM_SMEM ((2 * 128 * 40 + 2 * 240 * 40) * 2 + 2 * 240 * 4)
#define GEMM_GRID 296

__global__ void __launch_bounds__(384) gemm_kernel(
    const float* __restrict__ bias,
    const float* __restrict__ gamma,
    const float* __restrict__ beta,
    const float* __restrict__ bmean,
    const float* __restrict__ bvar)
{
    int nrows = g_nrows;
    int ntiles = (nrows + 127) >> 7;

    extern __shared__ char dsmc[];
    __half* Ash = reinterpret_cast<__half*>(dsmc);            // [2][128][40]
    __half* Bsh = Ash + 2 * 128 * 40;                         // [2][240][40]
    float* sc_s = reinterpret_cast<float*>(Bsh + 2 * 240 * 40);  // [240]
    float* sc_o = sc_s + 240;

    int tid = threadIdx.x;

    if (tid < 240) {
        float s = gamma[tid] * rsqrtf(bvar[tid] + 1e-5f);
        sc_s[tid] = s;
        sc_o[tid] = (bias[tid] - bmean[tid]) * s + beta[tid];
    }

    int lane = tid & 31, warp = tid >> 5;
    int wm = warp & 3, wn = warp >> 2;        // 4 M-warps x 3 N-warps
    int grp = lane >> 2, qk = lane & 3;
    int am = tid >> 1, ah = (tid & 1) * 16;   // A loader (tid < 256): 16 halfs each

    for (int tile = blockIdx.x; tile < ntiles; tile += GEMM_GRID) {
        int row0 = tile << 7;

        float acc[2][10][4];
#pragma unroll
        for (int mt = 0; mt < 2; ++mt)
#pragma unroll
            for (int nt = 0; nt < 10; ++nt)
#pragma unroll
                for (int q = 0; q < 4; ++q) acc[mt][nt][q] = 0.f;

        auto load_stage = [&](int kt, int s) {
            int kg = kt * 32;                  // halfs
            if (tid < 256) {
                const __half* ap = g_A + (size_t)(row0 + am) * K2 + kg + ah;
                cpasync16(&ASH(s, am, ah), ap);
                cpasync16(&ASH(s, am, ah + 8), ap + 8);
            }
            // B tile: 240 rows x 32 halfs = 960 16B-chunks (4 per row)
#pragma unroll
            for (int i = 0; i < 3; ++i) {
                int idx = tid + 384 * i;
                if (idx < 960) {
                    int rowb = idx >> 2;
                    int c8 = (idx & 3) << 3;   // half offset
                    cpasync16(&BSH(s, rowb, c8), g_Wt + (size_t)rowb * K2 + kg + c8);
                }
            }
            cp_commit();
        };

        __syncthreads();      // protect smem reuse across tiles
        load_stage(0, 0);

        for (int kt = 0; kt < 15; ++kt) {
            int s = kt & 1;
            if (kt < 14) {
                load_stage(kt + 1, s ^ 1);
                cp_wait<1>();
            } else {
                cp_wait<0>();
            }
            __syncthreads();

#pragma unroll
            for (int ks = 0; ks < 2; ++ks) {
                int kb = ks * 16;
                uint32_t a[2][4], b[10][2];
#pragma unroll
                for (int mt = 0; mt < 2; ++mt) {
                    int r = wm * 32 + mt * 16 + grp;
                    a[mt][0] = *reinterpret_cast<uint32_t*>(&ASH(s, r, kb + 2 * qk));
                    a[mt][1] = *reinterpret_cast<uint32_t*>(&ASH(s, r + 8, kb + 2 * qk));
                    a[mt][2] = *reinterpret_cast<uint32_t*>(&ASH(s, r, kb + 8 + 2 * qk));
                    a[mt][3] = *reinterpret_cast<uint32_t*>(&ASH(s, r + 8, kb + 8 + 2 * qk));
                }
#pragma unroll
                for (int nt = 0; nt < 10; ++nt) {
                    int nc = wn * 80 + nt * 8 + grp;
                    b[nt][0] = *reinterpret_cast<uint32_t*>(&BSH(s, nc, kb + 2 * qk));
                    b[nt][1] = *reinterpret_cast<uint32_t*>(&BSH(s, nc, kb + 8 + 2 * qk));
                }
#pragma unroll
                for (int mt = 0; mt < 2; ++mt)
#pragma unroll
                    for (int nt = 0; nt < 10; ++nt)
                        mma_f16(acc[mt][nt], a[mt], b[nt]);
            }
            __syncthreads();
        }

        // epilogue: BN + swish -> compact g_Y[o][row]
#pragma unroll
        for (int mt = 0; mt < 2; ++mt) {
            int r0 = row0 + wm * 32 + mt * 16 + grp;
            int r1 = r0 + 8;
            bool v0 = r0 < nrows, v1 = r1 < nrows;
#pragma unroll
            for (int nt = 0; nt < 10; ++nt) {
                int ocl = wn * 80 + nt * 8 + 2 * qk;
#pragma unroll
                for (int h = 0; h < 2; ++h) {
                    int o = ocl + h;
                    float s = sc_s[o], off = sc_o[o];
                    size_t ocol = (size_t)o * MAXROWS;
                    if (v0) {
                        float y = acc[mt][nt][h] * s + off;
                        g_Y[ocol + r0] = y / (1.0f + expf(-y));
                    }
                    if (v1) {
                        float y = acc[mt][nt][2 + h] * s + off;
                        g_Y[ocol + r1] = y / (1.0f + expf(-y));
                    }
                }
            }
        }
    }
}

// ---------------- 6) final output: coalesced merge of g_Y + empty constants ----------------
__global__ void __launch_bounds__(256) write_out_kernel(
    const float* __restrict__ bias,
    const float* __restrict__ gamma,
    const float* __restrict__ beta,
    const float* __restrict__ bmean,
    const float* __restrict__ bvar,
    float* __restrict__ out)          // [B][240][V]
{
    __shared__ float s_empty[60];
    int t = threadIdx.x;
    int span = blockIdx.x;            // < B*V/1024
    int o0 = blockIdx.y * 60;
    int b = span >> 5;                // 32 spans per batch
    int v0 = (span & 31) << 10;

    if (t < 60) {
        int o = o0 + t;
        float s = gamma[o] * rsqrtf(bvar[o] + 1e-5f);
        float y = (bias[o] - bmean[o]) * s + beta[o];
        s_empty[t] = y / (1.0f + expf(-y));
    }
    int4 rows = *reinterpret_cast<const int4*>(g_vox2row + b * Vv + v0 + 4 * t);
    __syncthreads();

    size_t obase = (size_t)b * Cc * Vv + v0 + 4 * t;
    for (int j = 0; j < 60; ++j) {
        int o = o0 + j;
        float e = s_empty[j];
        const float* ycol = g_Y + (size_t)o * MAXROWS;
        float4 r;
        r.x = (rows.x >= 0) ? ycol[rows.x] : e;
        r.y = (rows.y >= 0) ? ycol[rows.y] : e;
        r.z = (rows.z >= 0) ? ycol[rows.z] : e;
        r.w = (rows.w >= 0) ? ycol[rows.w] : e;
        __stcs(reinterpret_cast<float4*>(out + obase + (size_t)o * Vv), r);
    }
}

// ---------------- launch ----------------
extern "C" void kernel_launch(void* const* d_in, const int* in_sizes, int n_in,
                              void* d_out, int out_size) {
    const float* features = (const float*)d_in[0];
    const float* coords   = (const float*)d_in[1];
    const float* conv_w   = (const float*)d_in[2];
    const float* conv_b   = (const float*)d_in[3];
    const float* bn_gamma = (const float*)d_in[4];
    const float* bn_beta  = (const float*)d_in[5];
    const float* bn_mean  = (const float*)d_in[6];
    const float* bn_var   = (const float*)d_in[7];

    float* out = (float*)d_out;                       // [B, C, R^3]
    float* nc_out = out + (size_t)Bn * Cc * Vv;       // [B, 3, N]

    cudaFuncSetAttribute(gemm_kernel, cudaFuncAttributeMaxDynamicSharedMemorySize, GEMM_SMEM);

    init_stats_kernel<<<264, 1024>>>(conv_w, coords);
    points_kernel<<<(Bn * Nn) / 256, 256>>>(coords, nc_out);
    scan1_kernel<<<1024, 256>>>();
    scan3_kernel<<<1024, 256>>>();
    gtrans_kernel<<<dim3(Nn / 128, 5, Bn), 256>>>(features);
    reduce_kernel<<<1024, 256>>>();
    gemm_kernel<<<GEMM_GRID, 384, GEMM_SMEM>>>(conv_b, bn_gamma, bn_beta,
                                               bn_mean, bn_var);
    write_out_kernel<<<dim3((Bn * Vv) / 1024, 4), 256>>>(conv_b, bn_gamma, bn_beta,
                                                         bn_mean, bn_var, out);
}

// round 17
// speedup vs baseline: 1.8855x; 1.0281x over previous
#include <cuda_runtime.h>
#include <cuda_fp16.h>
#include <cstdint>
#include <climits>
#include <cmath>

#define Bn 8
#define Cc 240
#define Nn 16384
#define Rr 32
#define Vv 32768              // R^3
#define K2 480                // 2*C
#define FSH 256               // padded row stride of g_featT (halfs)
#define MAXROWS (Bn * Nn)     // worst case (131072)

// ---------------- scratch (static device globals; no allocations) ----------------
__device__ __half g_featT[(size_t)Bn * Nn * FSH]; // CSR-ordered point features, fp16 [slot][256]
__device__ __half g_A[(size_t)MAXROWS * K2];      // compact GEMM A, fp16 [row][max240|avg240]
__device__ __half g_Y[(size_t)Cc * MAXROWS];      // compact GEMM result fp16, col-major [o][row]
__device__ __half g_Wt[Cc * K2];                  // fp16 weights
__device__ int   g_cnt[Bn * Vv];
__device__ int   g_idx[Bn * Nn];                  // packed: idx (15b) | arrival (14b)
__device__ int   g_vox2row[Bn * Vv];              // -1 if empty
__device__ int   g_rowoff[MAXROWS];
__device__ int   g_rowcnt[MAXROWS];
__device__ unsigned long long g_bsum[1024];       // packed (rows<<32)|points per 256-voxel block
__device__ int   g_nrows;
__device__ float g_stats[Bn * 4];

__device__ __forceinline__ void mma_f16(float* c, const uint32_t* a, const uint32_t* b) {
    asm volatile(
        "mma.sync.aligned.m16n8k16.row.col.f32.f16.f16.f32 "
        "{%0,%1,%2,%3}, {%4,%5,%6,%7}, {%8,%9}, {%0,%1,%2,%3};"
        : "+f"(c[0]), "+f"(c[1]), "+f"(c[2]), "+f"(c[3])
        : "r"(a[0]), "r"(a[1]), "r"(a[2]), "r"(a[3]), "r"(b[0]), "r"(b[1]));
}

__device__ __forceinline__ void cpasync16(void* smem_ptr, const void* gptr) {
    unsigned s = (unsigned)__cvta_generic_to_shared(smem_ptr);
    asm volatile("cp.async.cg.shared.global [%0], [%1], 16;" :: "r"(s), "l"(gptr));
}
__device__ __forceinline__ void cp_commit() { asm volatile("cp.async.commit_group;"); }
template <int N>
__device__ __forceinline__ void cp_wait() { asm volatile("cp.async.wait_group %0;" :: "n"(N)); }

// ---------------- 0) fused: zero counters + fp16 W (blocks 0-255) | per-batch stats (256-263) ----
__global__ void __launch_bounds__(1024) init_stats_kernel(const float* __restrict__ W,
                                                          const float* __restrict__ coords) {
    int t = threadIdx.x;
    if (blockIdx.x < 256) {
        int i = blockIdx.x * 1024 + t;                // < B*V
        g_cnt[i] = 0;
        g_vox2row[i] = -1;
        if (i < Cc * K2) g_Wt[i] = __float2half_rn(W[i]);
        return;
    }
    // ---- stats for batch b ----
    int b = blockIdx.x - 256;
    __shared__ float wsm[96];
    __shared__ float smean[3];
    int lane = t & 31, w = t >> 5;
    const float* cx = coords + (size_t)b * 3 * Nn;
    float sx = 0.f, sy = 0.f, sz = 0.f;
    for (int n = t; n < Nn; n += 1024) {
        sx += cx[n];
        sy += cx[Nn + n];
        sz += cx[2 * Nn + n];
    }
#pragma unroll
    for (int d = 16; d; d >>= 1) {
        sx += __shfl_down_sync(0xffffffffu, sx, d);
        sy += __shfl_down_sync(0xffffffffu, sy, d);
        sz += __shfl_down_sync(0xffffffffu, sz, d);
    }
    if (lane == 0) { wsm[w] = sx; wsm[32 + w] = sy; wsm[64 + w] = sz; }
    __syncthreads();
    if (w == 0) {
        float a = wsm[lane], bb = wsm[32 + lane], c = wsm[64 + lane];
#pragma unroll
        for (int d = 16; d; d >>= 1) {
            a += __shfl_down_sync(0xffffffffu, a, d);
            bb += __shfl_down_sync(0xffffffffu, bb, d);
            c += __shfl_down_sync(0xffffffffu, c, d);
        }
        if (lane == 0) {
            smean[0] = a / (float)Nn;
            smean[1] = bb / (float)Nn;
            smean[2] = c / (float)Nn;
        }
    }
    __syncthreads();
    float mx = smean[0], my = smean[1], mz = smean[2];
    float mn = 0.f;
    for (int n = t; n < Nn; n += 1024) {
        float x = cx[n] - mx, y = cx[Nn + n] - my, z = cx[2 * Nn + n] - mz;
        mn = fmaxf(mn, sqrtf(x * x + y * y + z * z));
    }
#pragma unroll
    for (int d = 16; d; d >>= 1) mn = fmaxf(mn, __shfl_down_sync(0xffffffffu, mn, d));
    if (lane == 0) wsm[w] = mn;
    __syncthreads();
    if (w == 0) {
        float a = wsm[lane];
#pragma unroll
        for (int d = 16; d; d >>= 1) a = fmaxf(a, __shfl_down_sync(0xffffffffu, a, d));
        if (lane == 0) {
            g_stats[b * 4 + 0] = mx;
            g_stats[b * 4 + 1] = my;
            g_stats[b * 4 + 2] = mz;
            g_stats[b * 4 + 3] = a * 2.0f;   // denom (EPS = 0)
        }
    }
}

// ---------------- 1) normalized coords + packed voxel idx/arrival + counts ----------------
__global__ void points_kernel(const float* __restrict__ coords, float* __restrict__ nc_out) {
    int i = blockIdx.x * blockDim.x + threadIdx.x;   // < B*N
    int b = i >> 14;
    int n = i & (Nn - 1);
    float mx = g_stats[b * 4 + 0], my = g_stats[b * 4 + 1];
    float mz = g_stats[b * 4 + 2], dn = g_stats[b * 4 + 3];
    const float* cb = coords + (size_t)b * 3 * Nn;
    float x = cb[n], y = cb[Nn + n], z = cb[2 * Nn + n];

    float ncx = ((x - mx) / dn + 0.5f) * (float)Rr;
    float ncy = ((y - my) / dn + 0.5f) * (float)Rr;
    float ncz = ((z - mz) / dn + 0.5f) * (float)Rr;
    ncx = fminf(fmaxf(ncx, 0.f), (float)(Rr - 1));
    ncy = fminf(fmaxf(ncy, 0.f), (float)(Rr - 1));
    ncz = fminf(fmaxf(ncz, 0.f), (float)(Rr - 1));

    float* nb = nc_out + (size_t)b * 3 * Nn;
    nb[n] = ncx;
    nb[Nn + n] = ncy;
    nb[2 * Nn + n] = ncz;

    int vx = (int)rintf(ncx);   // round-half-even == jnp.round
    int vy = (int)rintf(ncy);
    int vz = (int)rintf(ncz);
    int idx = vx * (Rr * Rr) + vy * Rr + vz;
    int arr = atomicAdd(&g_cnt[b * Vv + idx], 1);    // arrival index (order-independent content)
    g_idx[i] = idx | (arr << 15);
}

// ---------------- 2a) block totals (256 voxels/block) ----------------
__global__ void scan1_kernel() {
    int blk = blockIdx.x, t = threadIdx.x;
    int cnt = g_cnt[blk * 256 + t];
    unsigned long long v = ((unsigned long long)(cnt > 0) << 32) | (unsigned)cnt;
#pragma unroll
    for (int d = 16; d; d >>= 1) v += __shfl_down_sync(0xffffffffu, v, d);
    __shared__ unsigned long long w[8];
    if ((t & 31) == 0) w[t >> 5] = v;
    __syncthreads();
    if (t == 0) {
        unsigned long long s = 0;
#pragma unroll
        for (int i = 0; i < 8; ++i) s += w[i];
        g_bsum[blk] = s;
    }
}

// ---------------- 2b) rows+offsets: every block redundantly scans the 1024 bsums ----------------
__global__ void scan3_kernel() {
    int blk = blockIdx.x, t = threadIdx.x, lane = t & 31, w = t >> 5;

    __shared__ unsigned long long part[256];
    {
        const unsigned long long* bs = g_bsum + 4 * t;
        part[t] = bs[0] + bs[1] + bs[2] + bs[3];
    }
    __syncthreads();
    unsigned long long x = part[t];
#pragma unroll
    for (int d = 1; d < 32; d <<= 1) {
        unsigned long long y = __shfl_up_sync(0xffffffffu, x, d);
        if (lane >= d) x += y;
    }
    __shared__ unsigned long long wsum[8];
    if (lane == 31) wsum[w] = x;
    __syncthreads();
    __shared__ unsigned long long wexc[8];
    if (t < 8) {
        unsigned long long s = 0;
        for (int i = 0; i < t; ++i) s += wsum[i];
        wexc[t] = s;
    }
    __syncthreads();
    __shared__ unsigned long long s_base, s_total;
    if (t == (blk >> 2)) {
        unsigned long long excl_chunk = x - part[t] + wexc[w];
        const unsigned long long* bs = g_bsum + (blk & ~3);
        for (int i = 0; i < (blk & 3); ++i) excl_chunk += bs[i];
        s_base = excl_chunk;
    }
    if (t == 255) s_total = x + wexc[7];
    __syncthreads();
    if (blk == 0 && t == 0) g_nrows = (int)(s_total >> 32);

    int bv = blk * 256 + t;
    int cnt = g_cnt[bv];
    unsigned long long v = ((unsigned long long)(cnt > 0) << 32) | (unsigned)cnt;
    unsigned long long orig = v;
#pragma unroll
    for (int d = 1; d < 32; d <<= 1) {
        unsigned long long y = __shfl_up_sync(0xffffffffu, v, d);
        if (lane >= d) v += y;
    }
    __syncthreads();
    if (lane == 31) wsum[w] = v;
    __syncthreads();
    if (t < 8) {
        unsigned long long s = 0;
        for (int i = 0; i < t; ++i) s += wsum[i];
        wexc[t] = s;
    }
    __syncthreads();
    unsigned long long excl = v - orig + wexc[w] + s_base;
    if (cnt > 0) {
        int row = (int)(excl >> 32);
        int off = (int)(excl & 0xffffffffu);
        g_vox2row[bv] = row;
        g_rowcnt[row] = cnt;
        g_rowoff[row] = off;
    }
}

// ---------------- 3) gather-transpose -> fp16 CSR rows; coalesced stores + smem swizzle ------
__global__ void __launch_bounds__(256) gtrans_kernel(const float* __restrict__ f) {
    __shared__ float4 sm4[48][32];
    __shared__ int s_slot[128];
    int b = blockIdx.z;
    int n0 = blockIdx.x << 7;
    int c0 = blockIdx.y * 48;
    int t = threadIdx.x;

    if (t < 128) {
        int pk = g_idx[(b << 14) + n0 + t];
        int idx = pk & 0x7fff;
        int row = g_vox2row[b * Vv + idx];
        s_slot[t] = g_rowoff[row] + (pk >> 15);
    }

    int col4 = t & 31, r0 = t >> 5;
#pragma unroll
    for (int rr = 0; rr < 6; ++rr) {
        int r = r0 + rr * 8;
        float4 v = __ldcs(reinterpret_cast<const float4*>(
            f + ((size_t)b * Cc + c0 + r) * Nn + n0 + col4 * 4));
        sm4[r][(col4 + r + (r >> 2)) & 31] = v;
    }
    __syncthreads();

    const float* smf = reinterpret_cast<const float*>(sm4);
#pragma unroll
    for (int it = 0; it < 6; ++it) {
        int w = it * 256 + t;
        int j = w % 12;
        int p = w / 12;
        int pq = p >> 2, pk = p & 3;
        float o[4];
#pragma unroll
        for (int kk = 0; kk < 4; ++kk) {
            int r = 4 * j + kk;
            o[kk] = smf[r * 128 + (((pq + r + (r >> 2)) & 31) << 2) + pk];
        }
        __half2 h0 = __floats2half2_rn(o[0], o[1]);
        __half2 h1 = __floats2half2_rn(o[2], o[3]);
        uint2 pk2 = make_uint2(*reinterpret_cast<uint32_t*>(&h0),
                               *reinterpret_cast<uint32_t*>(&h1));
        *reinterpret_cast<uint2*>(
            reinterpret_cast<char*>(g_featT) + ((size_t)s_slot[p] * FSH + c0 + 4 * j) * 2) = pk2;
    }
}

// ---------------- 4) reduce: 8 row-groups per 256-block, fp16 CSR rows -> fp16 A --------------
__global__ void __launch_bounds__(256) reduce_kernel() {
    int nrows = g_nrows;
    int t = threadIdx.x & 31;            // lane within group (use 30)
    int grpi = threadIdx.x >> 5;         // 0..7
    if (t >= 30) return;
    for (int row = blockIdx.x * 8 + grpi; row < nrows; row += gridDim.x * 8) {
        int cnt = g_rowcnt[row];
        int off = g_rowoff[row];
        const uint4* base = reinterpret_cast<const uint4*>(
            reinterpret_cast<const char*>(g_featT) + ((size_t)off * FSH + 8 * t) * 2);
        float s[8], m[8];
#pragma unroll
        for (int c = 0; c < 8; ++c) { s[c] = 0.f; m[c] = -INFINITY; }
        for (int p = 0; p < cnt; ++p) {
            uint4 v = __ldcs(base + (size_t)p * (FSH / 8));
            uint32_t uu[4] = {v.x, v.y, v.z, v.w};
#pragma unroll
            for (int q = 0; q < 4; ++q) {
                float2 f2 = __half22float2(*reinterpret_cast<__half2*>(&uu[q]));
                m[2 * q]     = fmaxf(m[2 * q], f2.x);     s[2 * q]     += f2.x;
                m[2 * q + 1] = fmaxf(m[2 * q + 1], f2.y); s[2 * q + 1] += f2.y;
            }
        }
        float inv = 1.0f / (float)cnt;
        __half* arow = g_A + (size_t)row * K2;
        uint2 mp, ap;
        {
            __half2 h0 = __floats2half2_rn(m[0], m[1]);
            __half2 h1 = __floats2half2_rn(m[2], m[3]);
            mp = make_uint2(*reinterpret_cast<uint32_t*>(&h0), *reinterpret_cast<uint32_t*>(&h1));
            *reinterpret_cast<uint2*>(arow + 8 * t) = mp;
            h0 = __floats2half2_rn(m[4], m[5]);
            h1 = __floats2half2_rn(m[6], m[7]);
            mp = make_uint2(*reinterpret_cast<uint32_t*>(&h0), *reinterpret_cast<uint32_t*>(&h1));
            *reinterpret_cast<uint2*>(arow + 8 * t + 4) = mp;
            h0 = __floats2half2_rn(s[0] * inv, s[1] * inv);
            h1 = __floats2half2_rn(s[2] * inv, s[3] * inv);
            ap = make_uint2(*reinterpret_cast<uint32_t*>(&h0), *reinterpret_cast<uint32_t*>(&h1));
            *reinterpret_cast<uint2*>(arow + Cc + 8 * t) = ap;
            h0 = __floats2half2_rn(s[4] * inv, s[5] * inv);
            h1 = __floats2half2_rn(s[6] * inv, s[7] * inv);
            ap = make_uint2(*reinterpret_cast<uint32_t*>(&h0), *reinterpret_cast<uint32_t*>(&h1));
            *reinterpret_cast<uint2*>(arow + Cc + 8 * t + 4) = ap;
        }
    }
}

// ---------------- 5) fp16 GEMM (m16n8k16) single-pass N=240, persistent -> fp16 g_Y -----------
// BM=128, BN=240, BK=32; 384 threads = 12 warps (4M x 3N); warp tile 32x80.
#define ASH(s, r, k) Ash[(((s) * 128 + (r)) * 40) + (k)]
#define BSH(s, r, k) Bsh[(((s) * 240 + (r)) * 40) + (k)]
#define GEMM_SMEM ((2 * 128 * 40 + 2 * 240 * 40) * 2 + 2 * 240 * 4)
#define GEMM_GRID 296

__global__ void __launch_bounds__(384) gemm_kernel(
    const float* __restrict__ bias,
    const float* __restrict__ gamma,
    const float* __restrict__ beta,
    const float* __restrict__ bmean,
    const float* __restrict__ bvar)
{
    int nrows = g_nrows;
    int ntiles = (nrows + 127) >> 7;

    extern __shared__ char dsmc[];
    __half* Ash = reinterpret_cast<__half*>(dsmc);            // [2][128][40]
    __half* Bsh = Ash + 2 * 128 * 40;                         // [2][240][40]
    float* sc_s = reinterpret_cast<float*>(Bsh + 2 * 240 * 40);  // [240]
    float* sc_o = sc_s + 240;

    int tid = threadIdx.x;

    if (tid < 240) {
        float s = gamma[tid] * rsqrtf(bvar[tid] + 1e-5f);
        sc_s[tid] = s;
        sc_o[tid] = (bias[tid] - bmean[tid]) * s + beta[tid];
    }

    int lane = tid & 31, warp = tid >> 5;
    int wm = warp & 3, wn = warp >> 2;        // 4 M-warps x 3 N-warps
    int grp = lane >> 2, qk = lane & 3;
    int am = tid >> 1, ah = (tid & 1) * 16;   // A loader (tid < 256): 16 halfs each

    for (int tile = blockIdx.x; tile < ntiles; tile += GEMM_GRID) {
        int row0 = tile << 7;

        float acc[2][10][4];
#pragma unroll
        for (int mt = 0; mt < 2; ++mt)
#pragma unroll
            for (int nt = 0; nt < 10; ++nt)
#pragma unroll
                for (int q = 0; q < 4; ++q) acc[mt][nt][q] = 0.f;

        auto load_stage = [&](int kt, int s) {
            int kg = kt * 32;                  // halfs
            if (tid < 256) {
                const __half* ap = g_A + (size_t)(row0 + am) * K2 + kg + ah;
                cpasync16(&ASH(s, am, ah), ap);
                cpasync16(&ASH(s, am, ah + 8), ap + 8);
            }
#pragma unroll
            for (int i = 0; i < 3; ++i) {
                int idx = tid + 384 * i;
                if (idx < 960) {
                    int rowb = idx >> 2;
                    int c8 = (idx & 3) << 3;   // half offset
                    cpasync16(&BSH(s, rowb, c8), g_Wt + (size_t)rowb * K2 + kg + c8);
                }
            }
            cp_commit();
        };

        __syncthreads();      // protect smem reuse across tiles
        load_stage(0, 0);

        for (int kt = 0; kt < 15; ++kt) {
            int s = kt & 1;
            if (kt < 14) {
                load_stage(kt + 1, s ^ 1);
                cp_wait<1>();
            } else {
                cp_wait<0>();
            }
            __syncthreads();

#pragma unroll
            for (int ks = 0; ks < 2; ++ks) {
                int kb = ks * 16;
                uint32_t a[2][4], b[10][2];
#pragma unroll
                for (int mt = 0; mt < 2; ++mt) {
                    int r = wm * 32 + mt * 16 + grp;
                    a[mt][0] = *reinterpret_cast<uint32_t*>(&ASH(s, r, kb + 2 * qk));
                    a[mt][1] = *reinterpret_cast<uint32_t*>(&ASH(s, r + 8, kb + 2 * qk));
                    a[mt][2] = *reinterpret_cast<uint32_t*>(&ASH(s, r, kb + 8 + 2 * qk));
                    a[mt][3] = *reinterpret_cast<uint32_t*>(&ASH(s, r + 8, kb + 8 + 2 * qk));
                }
#pragma unroll
                for (int nt = 0; nt < 10; ++nt) {
                    int nc = wn * 80 + nt * 8 + grp;
                    b[nt][0] = *reinterpret_cast<uint32_t*>(&BSH(s, nc, kb + 2 * qk));
                    b[nt][1] = *reinterpret_cast<uint32_t*>(&BSH(s, nc, kb + 8 + 2 * qk));
                }
#pragma unroll
                for (int mt = 0; mt < 2; ++mt)
#pragma unroll
                    for (int nt = 0; nt < 10; ++nt)
                        mma_f16(acc[mt][nt], a[mt], b[nt]);
            }
            __syncthreads();
        }

        // epilogue: BN + swish -> compact fp16 g_Y[o][row]
#pragma unroll
        for (int mt = 0; mt < 2; ++mt) {
            int r0 = row0 + wm * 32 + mt * 16 + grp;
            int r1 = r0 + 8;
            bool v0 = r0 < nrows, v1 = r1 < nrows;
#pragma unroll
            for (int nt = 0; nt < 10; ++nt) {
                int ocl = wn * 80 + nt * 8 + 2 * qk;
#pragma unroll
                for (int h = 0; h < 2; ++h) {
                    int o = ocl + h;
                    float s = sc_s[o], off = sc_o[o];
                    size_t ocol = (size_t)o * MAXROWS;
                    if (v0) {
                        float y = acc[mt][nt][h] * s + off;
                        g_Y[ocol + r0] = __float2half_rn(y / (1.0f + expf(-y)));
                    }
                    if (v1) {
                        float y = acc[mt][nt][2 + h] * s + off;
                        g_Y[ocol + r1] = __float2half_rn(y / (1.0f + expf(-y)));
                    }
                }
            }
        }
    }
}

// ---------------- 6) final output: coalesced merge of fp16 g_Y + empty constants ----------------
__global__ void __launch_bounds__(256) write_out_kernel(
    const float* __restrict__ bias,
    const float* __restrict__ gamma,
    const float* __restrict__ beta,
    const float* __restrict__ bmean,
    const float* __restrict__ bvar,
    float* __restrict__ out)          // [B][240][V]
{
    __shared__ float s_empty[60];
    int t = threadIdx.x;
    int span = blockIdx.x;            // < B*V/1024
    int o0 = blockIdx.y * 60;
    int b = span >> 5;                // 32 spans per batch
    int v0 = (span & 31) << 10;

    if (t < 60) {
        int o = o0 + t;
        float s = gamma[o] * rsqrtf(bvar[o] + 1e-5f);
        float y = (bias[o] - bmean[o]) * s + beta[o];
        s_empty[t] = y / (1.0f + expf(-y));
    }
    int4 rows = *reinterpret_cast<const int4*>(g_vox2row + b * Vv + v0 + 4 * t);
    __syncthreads();

    size_t obase = (size_t)b * Cc * Vv + v0 + 4 * t;
    for (int j = 0; j < 60; ++j) {
        int o = o0 + j;
        float e = s_empty[j];
        const __half* ycol = g_Y + (size_t)o * MAXROWS;
        float4 r;
        r.x = (rows.x >= 0) ? __half2float(ycol[rows.x]) : e;
        r.y = (rows.y >= 0) ? __half2float(ycol[rows.y]) : e;
        r.z = (rows.z >= 0) ? __half2float(ycol[rows.z]) : e;
        r.w = (rows.w >= 0) ? __half2float(ycol[rows.w]) : e;
        __stcs(reinterpret_cast<float4*>(out + obase + (size_t)o * Vv), r);
    }
}

// ---------------- launch ----------------
extern "C" void kernel_launch(void* const* d_in, const int* in_sizes, int n_in,
                              void* d_out, int out_size) {
    const float* features = (const float*)d_in[0];
    const float* coords   = (const float*)d_in[1];
    const float* conv_w   = (const float*)d_in[2];
    const float* conv_b   = (const float*)d_in[3];
    const float* bn_gamma = (const float*)d_in[4];
    const float* bn_beta  = (const float*)d_in[5];
    const float* bn_mean  = (const float*)d_in[6];
    const float* bn_var   = (const float*)d_in[7];

    float* out = (float*)d_out;                       // [B, C, R^3]
    float* nc_out = out + (size_t)Bn * Cc * Vv;       // [B, 3, N]

    cudaFuncSetAttribute(gemm_kernel, cudaFuncAttributeMaxDynamicSharedMemorySize, GEMM_SMEM);

    init_stats_kernel<<<264, 1024>>>(conv_w, coords);
    points_kernel<<<(Bn * Nn) / 256, 256>>>(coords, nc_out);
    scan1_kernel<<<1024, 256>>>();
    scan3_kernel<<<1024, 256>>>();
    gtrans_kernel<<<dim3(Nn / 128, 5, Bn), 256>>>(features);
    reduce_kernel<<<1024, 256>>>();
    gemm_kernel<<<GEMM_GRID, 384, GEMM_SMEM>>>(conv_b, bn_gamma, bn_beta,
                                               bn_mean, bn_var);
    write_out_kernel<<<dim3((Bn * Vv) / 1024, 4), 256>>>(conv_b, bn_gamma, bn_beta,
                                                         bn_mean, bn_var, out);
}